// round 1
// baseline (speedup 1.0000x reference)
#include <cuda_runtime.h>
#include <cuda_bf16.h>

// ---------------------------------------------------------------------------
// fc_lstm: 3-layer LSTM encoder/decoder, HID=2048, B=64, 16 enc + 16 dec steps
// Round 1: fp32 SGEMM with K-split + atomic accumulation. Correctness-first.
// ---------------------------------------------------------------------------

#define BM 64
#define BN 64
#define BK 16

// Scratch (allocation-free: __device__ globals)
__device__ __align__(16) float g_buf1[64 * 1024];       // FC intermediate (1024)
__device__ __align__(16) float g_x[64 * 2048];          // FC2 output (2048)
__device__ __align__(16) float g_gates[64 * 8192];      // LSTM gate accumulator
__device__ __align__(16) float g_h[3 * 64 * 2048];      // hidden states
__device__ __align__(16) float g_c[3 * 64 * 2048];      // cell states
__device__ __align__(16) float g_zero[64 * 2048];       // zero input for dec t=0

// C[m, n] = bias[n]  (accumulator init; N is a power of two)
__global__ void init_bias_kernel(float* __restrict__ C, const float* __restrict__ b, int N) {
    int idx = blockIdx.x * 256 + threadIdx.x;
    C[idx] = b[idx & (N - 1)];
}

// C[64, N] += act(A0)[64,K0] @ W0[N,K0]^T  (+ A1[64,K1] @ W1[N,K1]^T)
// Atomic accumulation over blockIdx.y K-chunks. Tile 64x64, 64 threads, 8x8
// interleaved microtile (stride-8 register tiles -> conflict-free scalar LDS).
__global__ void gemm_kernel(const float* __restrict__ A0, const float* __restrict__ W0,
                            int K0, int reluA0,
                            const float* __restrict__ A1, const float* __restrict__ W1, int K1,
                            float* __restrict__ C, int N, int kchunk)
{
    __shared__ float As[BK][BM];
    __shared__ float Bs[BK][BN];
    const int t  = threadIdx.x;          // 0..63
    const int tx = t & 7;
    const int ty = t >> 3;
    const int nbase = blockIdx.x * BN;
    const int kbeg  = blockIdx.y * kchunk;
    const int kend  = kbeg + kchunk;     // host guarantees exact division

    float acc[8][8];
#pragma unroll
    for (int i = 0; i < 8; i++)
#pragma unroll
        for (int j = 0; j < 8; j++) acc[i][j] = 0.f;

    for (int kb = kbeg; kb < kend; kb += BK) {
        // segment select (K0 and K1 are multiples of BK)
        const float* A; const float* W; int KA, kl, rel;
        if (kb < K0) { A = A0; W = W0; KA = K0; kl = kb;      rel = reluA0; }
        else         { A = A1; W = W1; KA = K1; kl = kb - K0; rel = 0;      }

        const float4* ar = reinterpret_cast<const float4*>(A + (size_t)t * KA + kl);
        const float4* wr = reinterpret_cast<const float4*>(W + (size_t)(nbase + t) * KA + kl);
#pragma unroll
        for (int i = 0; i < 4; i++) {
            float4 v = ar[i];
            if (rel) {
                v.x = fmaxf(v.x, 0.f); v.y = fmaxf(v.y, 0.f);
                v.z = fmaxf(v.z, 0.f); v.w = fmaxf(v.w, 0.f);
            }
            As[4 * i + 0][t] = v.x; As[4 * i + 1][t] = v.y;
            As[4 * i + 2][t] = v.z; As[4 * i + 3][t] = v.w;
            float4 w = wr[i];
            Bs[4 * i + 0][t] = w.x; Bs[4 * i + 1][t] = w.y;
            Bs[4 * i + 2][t] = w.z; Bs[4 * i + 3][t] = w.w;
        }
        __syncthreads();
#pragma unroll
        for (int kk = 0; kk < BK; kk++) {
            float a[8], b[8];
#pragma unroll
            for (int i = 0; i < 8; i++) a[i] = As[kk][ty + 8 * i];
#pragma unroll
            for (int j = 0; j < 8; j++) b[j] = Bs[kk][tx + 8 * j];
#pragma unroll
            for (int i = 0; i < 8; i++)
#pragma unroll
                for (int j = 0; j < 8; j++)
                    acc[i][j] = fmaf(a[i], b[j], acc[i][j]);
        }
        __syncthreads();
    }

#pragma unroll
    for (int i = 0; i < 8; i++) {
        int m = ty + 8 * i;
#pragma unroll
        for (int j = 0; j < 8; j++) {
            atomicAdd(&C[(size_t)m * N + nbase + tx + 8 * j], acc[i][j]);
        }
    }
}

// LSTM pointwise: gates[64,8192] split (i,f,g,o), c/h in place. idx over 64*2048.
__global__ void lstm_ew_kernel(const float* __restrict__ gates,
                               float* __restrict__ h, float* __restrict__ c)
{
    int idx = blockIdx.x * 256 + threadIdx.x;
    int m = idx >> 11, j = idx & 2047;
    const float* g = gates + (size_t)m * 8192 + j;
    float vi = g[0], vf = g[2048], vg = g[4096], vo = g[6144];
    float si = 1.f / (1.f + __expf(-vi));
    float sf = 1.f / (1.f + __expf(-vf));
    float so = 1.f / (1.f + __expf(-vo));
    float tg = tanhf(vg);
    float c2 = sf * c[idx] + si * tg;
    float h2 = so * tanhf(c2);
    c[idx] = c2;
    h[idx] = h2;
}

__global__ void sigmoid_kernel(float* __restrict__ y) {
    int idx = blockIdx.x * 256 + threadIdx.x;
    float v = y[idx];
    y[idx] = 1.f / (1.f + __expf(-v));
}

extern "C" void kernel_launch(void* const* d_in, const int* in_sizes, int n_in,
                              void* d_out, int out_size)
{
    const float* x        = (const float*)d_in[0];   // [16,64,64,64]
    const float* fc_en1_w = (const float*)d_in[1];   // [1024,4096]
    const float* fc_en1_b = (const float*)d_in[2];
    const float* fc_en2_w = (const float*)d_in[3];   // [2048,1024]
    const float* fc_en2_b = (const float*)d_in[4];
    const float* en_wih   = (const float*)d_in[5];   // [3,8192,2048]
    const float* en_whh   = (const float*)d_in[6];
    const float* en_b     = (const float*)d_in[7];   // [3,8192]
    const float* de_wih   = (const float*)d_in[8];
    const float* de_whh   = (const float*)d_in[9];
    const float* de_b     = (const float*)d_in[10];
    const float* fc_de1_w = (const float*)d_in[11];  // [1024,2048]
    const float* fc_de1_b = (const float*)d_in[12];
    const float* fc_de2_w = (const float*)d_in[13];  // [4096,1024]
    const float* fc_de2_b = (const float*)d_in[14];
    float* out = (float*)d_out;                      // [16,64,4096]

    float *buf1, *xb, *gates, *h, *c, *zero;
    cudaGetSymbolAddress((void**)&buf1,  g_buf1);
    cudaGetSymbolAddress((void**)&xb,    g_x);
    cudaGetSymbolAddress((void**)&gates, g_gates);
    cudaGetSymbolAddress((void**)&h,     g_h);
    cudaGetSymbolAddress((void**)&c,     g_c);
    cudaGetSymbolAddress((void**)&zero,  g_zero);

    const size_t HB = (size_t)64 * 2048;   // one [64, H] slab
    const size_t LW = (size_t)8192 * 2048; // one [4H, H] weight matrix

    auto gemm = [&](const float* A0, const float* W0, int K0, int rel0,
                    const float* A1, const float* W1, int K1,
                    float* C, int N, int KS) {
        dim3 grid(N / BN, KS);
        gemm_kernel<<<grid, 64>>>(A0, W0, K0, rel0, A1, W1, K1, C, N, (K0 + K1) / KS);
    };
    auto initb = [&](float* C, const float* b, int N) {
        init_bias_kernel<<<(64 * N) / 256, 256>>>(C, b, N);
    };

    cudaMemsetAsync(h,    0, 3 * HB * sizeof(float));
    cudaMemsetAsync(c,    0, 3 * HB * sizeof(float));
    cudaMemsetAsync(zero, 0, HB * sizeof(float));

    // -------------------- encoder --------------------
    for (int t = 0; t < 16; t++) {
        const float* xt = x + (size_t)t * 64 * 4096;
        // FC1: [64,4096] -> [64,1024]  (relu deferred to consumer)
        initb(buf1, fc_en1_b, 1024);
        gemm(xt, fc_en1_w, 4096, 0, nullptr, nullptr, 0, buf1, 1024, 32);
        // FC2: relu(FC1) -> [64,2048]
        initb(xb, fc_en2_b, 2048);
        gemm(buf1, fc_en2_w, 1024, 1, nullptr, nullptr, 0, xb, 2048, 16);

        const float* inp = xb;
        int relin = 1;  // relu(FC2) applied on load by layer-0 gate GEMM
        for (int l = 0; l < 3; l++) {
            float* hl = h + l * HB;
            float* cl = c + l * HB;
            initb(gates, en_b + l * 8192, 8192);
            gemm(inp, en_wih + (size_t)l * LW, 2048, relin,
                 hl,  en_whh + (size_t)l * LW, 2048, gates, 8192, 4);
            lstm_ew_kernel<<<(64 * 2048) / 256, 256>>>(gates, hl, cl);
            inp = hl;
            relin = 0;
        }
    }

    // decoder init: h_d[0] = h_e[2]; everything else zero
    cudaMemcpyAsync(h, h + 2 * HB, HB * sizeof(float), cudaMemcpyDeviceToDevice);
    cudaMemsetAsync(h + HB, 0, 2 * HB * sizeof(float));
    cudaMemsetAsync(c, 0, 3 * HB * sizeof(float));

    // -------------------- decoder --------------------
    for (int t = 0; t < 16; t++) {
        // feedback: input = previous step's h[2] (layer-2 h is overwritten only
        // after layer-0's GEMM has consumed it)
        const float* inp = (t == 0) ? zero : (h + 2 * HB);
        for (int l = 0; l < 3; l++) {
            float* hl = h + l * HB;
            float* cl = c + l * HB;
            initb(gates, de_b + l * 8192, 8192);
            gemm(inp, de_wih + (size_t)l * LW, 2048, 0,
                 hl,  de_whh + (size_t)l * LW, 2048, gates, 8192, 4);
            lstm_ew_kernel<<<(64 * 2048) / 256, 256>>>(gates, hl, cl);
            inp = hl;
        }
        float* ot = out + (size_t)t * 64 * 4096;
        // FC de1: [64,2048] -> [64,1024]
        initb(buf1, fc_de1_b, 1024);
        gemm(h + 2 * HB, fc_de1_w, 2048, 0, nullptr, nullptr, 0, buf1, 1024, 32);
        // FC de2: relu(de1) -> [64,4096], then sigmoid -> output
        initb(ot, fc_de2_b, 4096);
        gemm(buf1, fc_de2_w, 1024, 1, nullptr, nullptr, 0, ot, 4096, 8);
        sigmoid_kernel<<<(64 * 4096) / 256, 256>>>(ot);
    }
}

// round 2
// speedup vs baseline: 1.0021x; 1.0021x over previous
#include <cuda_runtime.h>
#include <cuda_bf16.h>

// ---------------------------------------------------------------------------
// fc_lstm: 3-layer LSTM encoder/decoder, HID=2048, B=64, 16 enc + 16 dec steps
// Round 1: fp32 SGEMM with K-split + atomic accumulation. Correctness-first.
// ---------------------------------------------------------------------------

#define BM 64
#define BN 64
#define BK 16

// Scratch (allocation-free: __device__ globals)
__device__ __align__(16) float g_buf1[64 * 1024];       // FC intermediate (1024)
__device__ __align__(16) float g_x[64 * 2048];          // FC2 output (2048)
__device__ __align__(16) float g_gates[64 * 8192];      // LSTM gate accumulator
__device__ __align__(16) float g_h[3 * 64 * 2048];      // hidden states
__device__ __align__(16) float g_c[3 * 64 * 2048];      // cell states
__device__ __align__(16) float g_zero[64 * 2048];       // zero input for dec t=0

// C[m, n] = bias[n]  (accumulator init; N is a power of two)
__global__ void init_bias_kernel(float* __restrict__ C, const float* __restrict__ b, int N) {
    int idx = blockIdx.x * 256 + threadIdx.x;
    C[idx] = b[idx & (N - 1)];
}

// C[64, N] += act(A0)[64,K0] @ W0[N,K0]^T  (+ A1[64,K1] @ W1[N,K1]^T)
// Atomic accumulation over blockIdx.y K-chunks. Tile 64x64, 64 threads, 8x8
// interleaved microtile (stride-8 register tiles -> conflict-free scalar LDS).
__global__ void gemm_kernel(const float* __restrict__ A0, const float* __restrict__ W0,
                            int K0, int reluA0,
                            const float* __restrict__ A1, const float* __restrict__ W1, int K1,
                            float* __restrict__ C, int N, int kchunk)
{
    __shared__ float As[BK][BM];
    __shared__ float Bs[BK][BN];
    const int t  = threadIdx.x;          // 0..63
    const int tx = t & 7;
    const int ty = t >> 3;
    const int nbase = blockIdx.x * BN;
    const int kbeg  = blockIdx.y * kchunk;
    const int kend  = kbeg + kchunk;     // host guarantees exact division

    float acc[8][8];
#pragma unroll
    for (int i = 0; i < 8; i++)
#pragma unroll
        for (int j = 0; j < 8; j++) acc[i][j] = 0.f;

    for (int kb = kbeg; kb < kend; kb += BK) {
        // segment select (K0 and K1 are multiples of BK)
        const float* A; const float* W; int KA, kl, rel;
        if (kb < K0) { A = A0; W = W0; KA = K0; kl = kb;      rel = reluA0; }
        else         { A = A1; W = W1; KA = K1; kl = kb - K0; rel = 0;      }

        const float4* ar = reinterpret_cast<const float4*>(A + (size_t)t * KA + kl);
        const float4* wr = reinterpret_cast<const float4*>(W + (size_t)(nbase + t) * KA + kl);
#pragma unroll
        for (int i = 0; i < 4; i++) {
            float4 v = ar[i];
            if (rel) {
                v.x = fmaxf(v.x, 0.f); v.y = fmaxf(v.y, 0.f);
                v.z = fmaxf(v.z, 0.f); v.w = fmaxf(v.w, 0.f);
            }
            As[4 * i + 0][t] = v.x; As[4 * i + 1][t] = v.y;
            As[4 * i + 2][t] = v.z; As[4 * i + 3][t] = v.w;
            float4 w = wr[i];
            Bs[4 * i + 0][t] = w.x; Bs[4 * i + 1][t] = w.y;
            Bs[4 * i + 2][t] = w.z; Bs[4 * i + 3][t] = w.w;
        }
        __syncthreads();
#pragma unroll
        for (int kk = 0; kk < BK; kk++) {
            float a[8], b[8];
#pragma unroll
            for (int i = 0; i < 8; i++) a[i] = As[kk][ty + 8 * i];
#pragma unroll
            for (int j = 0; j < 8; j++) b[j] = Bs[kk][tx + 8 * j];
#pragma unroll
            for (int i = 0; i < 8; i++)
#pragma unroll
                for (int j = 0; j < 8; j++)
                    acc[i][j] = fmaf(a[i], b[j], acc[i][j]);
        }
        __syncthreads();
    }

#pragma unroll
    for (int i = 0; i < 8; i++) {
        int m = ty + 8 * i;
#pragma unroll
        for (int j = 0; j < 8; j++) {
            atomicAdd(&C[(size_t)m * N + nbase + tx + 8 * j], acc[i][j]);
        }
    }
}

// LSTM pointwise: gates[64,8192] split (i,f,g,o), c/h in place. idx over 64*2048.
__global__ void lstm_ew_kernel(const float* __restrict__ gates,
                               float* __restrict__ h, float* __restrict__ c)
{
    int idx = blockIdx.x * 256 + threadIdx.x;
    int m = idx >> 11, j = idx & 2047;
    const float* g = gates + (size_t)m * 8192 + j;
    float vi = g[0], vf = g[2048], vg = g[4096], vo = g[6144];
    float si = 1.f / (1.f + __expf(-vi));
    float sf = 1.f / (1.f + __expf(-vf));
    float so = 1.f / (1.f + __expf(-vo));
    float tg = tanhf(vg);
    float c2 = sf * c[idx] + si * tg;
    float h2 = so * tanhf(c2);
    c[idx] = c2;
    h[idx] = h2;
}

__global__ void sigmoid_kernel(float* __restrict__ y) {
    int idx = blockIdx.x * 256 + threadIdx.x;
    float v = y[idx];
    y[idx] = 1.f / (1.f + __expf(-v));
}

extern "C" void kernel_launch(void* const* d_in, const int* in_sizes, int n_in,
                              void* d_out, int out_size)
{
    const float* x        = (const float*)d_in[0];   // [16,64,64,64]
    const float* fc_en1_w = (const float*)d_in[1];   // [1024,4096]
    const float* fc_en1_b = (const float*)d_in[2];
    const float* fc_en2_w = (const float*)d_in[3];   // [2048,1024]
    const float* fc_en2_b = (const float*)d_in[4];
    const float* en_wih   = (const float*)d_in[5];   // [3,8192,2048]
    const float* en_whh   = (const float*)d_in[6];
    const float* en_b     = (const float*)d_in[7];   // [3,8192]
    const float* de_wih   = (const float*)d_in[8];
    const float* de_whh   = (const float*)d_in[9];
    const float* de_b     = (const float*)d_in[10];
    const float* fc_de1_w = (const float*)d_in[11];  // [1024,2048]
    const float* fc_de1_b = (const float*)d_in[12];
    const float* fc_de2_w = (const float*)d_in[13];  // [4096,1024]
    const float* fc_de2_b = (const float*)d_in[14];
    float* out = (float*)d_out;                      // [16,64,4096]

    float *buf1, *xb, *gates, *h, *c, *zero;
    cudaGetSymbolAddress((void**)&buf1,  g_buf1);
    cudaGetSymbolAddress((void**)&xb,    g_x);
    cudaGetSymbolAddress((void**)&gates, g_gates);
    cudaGetSymbolAddress((void**)&h,     g_h);
    cudaGetSymbolAddress((void**)&c,     g_c);
    cudaGetSymbolAddress((void**)&zero,  g_zero);

    const size_t HB = (size_t)64 * 2048;   // one [64, H] slab
    const size_t LW = (size_t)8192 * 2048; // one [4H, H] weight matrix

    auto gemm = [&](const float* A0, const float* W0, int K0, int rel0,
                    const float* A1, const float* W1, int K1,
                    float* C, int N, int KS) {
        dim3 grid(N / BN, KS);
        gemm_kernel<<<grid, 64>>>(A0, W0, K0, rel0, A1, W1, K1, C, N, (K0 + K1) / KS);
    };
    auto initb = [&](float* C, const float* b, int N) {
        init_bias_kernel<<<(64 * N) / 256, 256>>>(C, b, N);
    };

    cudaMemsetAsync(h,    0, 3 * HB * sizeof(float));
    cudaMemsetAsync(c,    0, 3 * HB * sizeof(float));
    cudaMemsetAsync(zero, 0, HB * sizeof(float));

    // -------------------- encoder --------------------
    for (int t = 0; t < 16; t++) {
        const float* xt = x + (size_t)t * 64 * 4096;
        // FC1: [64,4096] -> [64,1024]  (relu deferred to consumer)
        initb(buf1, fc_en1_b, 1024);
        gemm(xt, fc_en1_w, 4096, 0, nullptr, nullptr, 0, buf1, 1024, 32);
        // FC2: relu(FC1) -> [64,2048]
        initb(xb, fc_en2_b, 2048);
        gemm(buf1, fc_en2_w, 1024, 1, nullptr, nullptr, 0, xb, 2048, 16);

        const float* inp = xb;
        int relin = 1;  // relu(FC2) applied on load by layer-0 gate GEMM
        for (int l = 0; l < 3; l++) {
            float* hl = h + l * HB;
            float* cl = c + l * HB;
            initb(gates, en_b + l * 8192, 8192);
            gemm(inp, en_wih + (size_t)l * LW, 2048, relin,
                 hl,  en_whh + (size_t)l * LW, 2048, gates, 8192, 4);
            lstm_ew_kernel<<<(64 * 2048) / 256, 256>>>(gates, hl, cl);
            inp = hl;
            relin = 0;
        }
    }

    // decoder init: h_d[0] = h_e[2]; everything else zero
    cudaMemcpyAsync(h, h + 2 * HB, HB * sizeof(float), cudaMemcpyDeviceToDevice);
    cudaMemsetAsync(h + HB, 0, 2 * HB * sizeof(float));
    cudaMemsetAsync(c, 0, 3 * HB * sizeof(float));

    // -------------------- decoder --------------------
    for (int t = 0; t < 16; t++) {
        // feedback: input = previous step's h[2] (layer-2 h is overwritten only
        // after layer-0's GEMM has consumed it)
        const float* inp = (t == 0) ? zero : (h + 2 * HB);
        for (int l = 0; l < 3; l++) {
            float* hl = h + l * HB;
            float* cl = c + l * HB;
            initb(gates, de_b + l * 8192, 8192);
            gemm(inp, de_wih + (size_t)l * LW, 2048, 0,
                 hl,  de_whh + (size_t)l * LW, 2048, gates, 8192, 4);
            lstm_ew_kernel<<<(64 * 2048) / 256, 256>>>(gates, hl, cl);
            inp = hl;
        }
        float* ot = out + (size_t)t * 64 * 4096;
        // FC de1: [64,2048] -> [64,1024]
        initb(buf1, fc_de1_b, 1024);
        gemm(h + 2 * HB, fc_de1_w, 2048, 0, nullptr, nullptr, 0, buf1, 1024, 32);
        // FC de2: relu(de1) -> [64,4096], then sigmoid -> output
        initb(ot, fc_de2_b, 4096);
        gemm(buf1, fc_de2_w, 1024, 1, nullptr, nullptr, 0, ot, 4096, 8);
        sigmoid_kernel<<<(64 * 4096) / 256, 256>>>(ot);
    }
}

// round 4
// speedup vs baseline: 2.8839x; 2.8779x over previous
#include <cuda_runtime.h>
#include <cuda_bf16.h>
#include <cstdint>
#include <cstddef>

typedef __nv_bfloat16 bf;

// ---------------- tile constants ----------------
#define TM    128
#define TN    64
#define KC    64
#define ROWB  144                 // padded SMEM row: 72 bf16 = 144 B (conflict-free ldmatrix)
#define AT_B  (128 * ROWB)        // 18432 B per A tile
#define BT_B  (64 * ROWB)         // 9216 B per B tile
#define OFF_AH 0
#define OFF_AL 18432
#define OFF_BH 36864
#define OFF_BL 46080
#define STAGE  55296
#define NSTAGE 3
#define SMEM_SZ (NSTAGE * STAGE)  // 165888; epilogue reuses (needs 33792)

// ---------------- asm helpers ----------------
__device__ __forceinline__ void cpa(uint32_t d, const void* s) {
    asm volatile("cp.async.cg.shared.global [%0], [%1], 16;" :: "r"(d), "l"(s));
}
__device__ __forceinline__ void cpcommit() {
    asm volatile("cp.async.commit_group;" ::: "memory");
}
template <int N> __device__ __forceinline__ void cpwait() {
    asm volatile("cp.async.wait_group %0;" :: "n"(N) : "memory");
}
#define LDSM4(R, addr) \
    asm volatile("ldmatrix.sync.aligned.m8n8.x4.shared.b16 {%0,%1,%2,%3}, [%4];" \
        : "=r"((R)[0]), "=r"((R)[1]), "=r"((R)[2]), "=r"((R)[3]) : "r"(addr))
#define MMA(D, A, b0, b1) \
    asm volatile("mma.sync.aligned.m16n8k16.row.col.f32.bf16.bf16.f32 " \
        "{%0,%1,%2,%3}, {%4,%5,%6,%7}, {%8,%9}, {%0,%1,%2,%3};" \
        : "+f"((D)[0]), "+f"((D)[1]), "+f"((D)[2]), "+f"((D)[3]) \
        : "r"((A)[0]), "r"((A)[1]), "r"((A)[2]), "r"((A)[3]), "r"(b0), "r"(b1))

// ---------------- scratch (__device__ globals; no allocations) ----------------
#define LWN 16777216               // 8192*2048
__device__ bf g_ewih_h[3*LWN], g_ewih_l[3*LWN];
__device__ bf g_ewhh_h[3*LWN], g_ewhh_l[3*LWN];
__device__ bf g_dwih_h[3*LWN], g_dwih_l[3*LWN];
__device__ bf g_dwhh_h[3*LWN], g_dwhh_l[3*LWN];
__device__ bf g_fc1w_h[4194304], g_fc1w_l[4194304];
__device__ bf g_fc2w_h[2097152], g_fc2w_l[2097152];
__device__ bf g_fd1w_h[2097152], g_fd1w_l[2097152];
__device__ bf g_fd2w_h[4194304], g_fd2w_l[4194304];
__device__ bf g_xh[4194304],    g_xl[4194304];        // [1024,4096]
__device__ bf g_f1a_h[1048576], g_f1a_l[1048576];     // [1024,1024]
__device__ bf g_f2a_h[2097152], g_f2a_l[2097152];     // [1024,2048]
__device__ bf g_d1a_h[65536],   g_d1a_l[65536];       // [64,1024]
__device__ bf g_ha_h[393216],   g_ha_l[393216];       // 3 x [64,2048]
__device__ bf g_zero[131072];
__device__ float g_gates0[524288], g_gates1[524288];  // [64,8192] batch-major
__device__ float g_c[393216];

// ===========================================================================
// Split-precision bf16 mma.sync GEMM.
//   D[f in 128-tile, b in 64-tile] = sum_k W[f,k]*act[b,k]  (3-term hi/lo)
// modes: 0 fp32 out (+bias if non-null); 1 relu + bf16 hi/lo split; 2 sigmoid
// dual: grid.y selects operand set (LSTM Wih/Whh); else grid.y = token tile.
// ===========================================================================
__global__ void __launch_bounds__(256, 1)
gemm_ms(const bf* __restrict__ Ah0, const bf* __restrict__ Al0,
        const bf* __restrict__ Bh0, const bf* __restrict__ Bl0,
        const float* __restrict__ bias0, float* __restrict__ out0,
        const bf* __restrict__ Ah1, const bf* __restrict__ Al1,
        const bf* __restrict__ Bh1, const bf* __restrict__ Bl1,
        const float* __restrict__ bias1, float* __restrict__ out1,
        bf* __restrict__ outh, bf* __restrict__ outl,
        int K, int ldc, int mode, int dual)
{
    extern __shared__ char smem[];
    const uint32_t sb = (uint32_t)__cvta_generic_to_shared(smem);
    const int t = threadIdx.x;
    const int fbase = blockIdx.x * TM;

    const bf *Ah, *Al, *Bh, *Bl; const float* bias; float* outf; int nbase;
    if (dual && blockIdx.y == 1) {
        Ah = Ah1; Al = Al1; Bh = Bh1; Bl = Bl1; bias = bias1; outf = out1; nbase = 0;
    } else {
        Ah = Ah0; Al = Al0; Bh = Bh0; Bl = Bl0; bias = bias0; outf = out0;
        nbase = dual ? 0 : blockIdx.y * TN;
    }
    const bf* aH = Ah + (size_t)fbase * K;
    const bf* aL = Al + (size_t)fbase * K;
    const bf* bH = Bh + (size_t)nbase * K;
    const bf* bL = Bl + (size_t)nbase * K;
    const int NC = K >> 6;

    const int r0 = t >> 3, seg = t & 7;
    auto issue = [&](int chunk) {
        const uint32_t st = sb + (chunk % NSTAGE) * STAGE;
        const int koff = (chunk << 6) + seg * 8;
#pragma unroll
        for (int i = 0; i < 4; i++) {
            int row = r0 + i * 32;
            uint32_t d = st + row * ROWB + seg * 16;
            cpa(d + OFF_AH, aH + (size_t)row * K + koff);
            cpa(d + OFF_AL, aL + (size_t)row * K + koff);
        }
#pragma unroll
        for (int i = 0; i < 2; i++) {
            int row = r0 + i * 32;
            uint32_t d = st + row * ROWB + seg * 16;
            cpa(d + OFF_BH, bH + (size_t)row * K + koff);
            cpa(d + OFF_BL, bL + (size_t)row * K + koff);
        }
    };

    issue(0); cpcommit();
    issue(1); cpcommit();
    issue(2); cpcommit();

    const int w = t >> 5, lane = t & 31;
    const int moff = (w & 3) * 32;
    const int noff = (w >> 2) * 32;
    // ldmatrix lane addressing
    const int arow = lane & 15, ahalf = lane >> 4;
    const int bj = lane >> 3;
    const int brow = ((bj >> 1) * 8) + (lane & 7), bkh = bj & 1;

    float d[2][4][4];
#pragma unroll
    for (int mi = 0; mi < 2; mi++)
#pragma unroll
        for (int nj = 0; nj < 4; nj++)
#pragma unroll
            for (int q = 0; q < 4; q++) d[mi][nj][q] = 0.f;

    for (int s = 0; s < NC; s++) {
        cpwait<2>();
        __syncthreads();
        const uint32_t st = sb + (s % NSTAGE) * STAGE;
#pragma unroll
        for (int k16 = 0; k16 < 4; k16++) {
            const int kb = k16 * 32;
            uint32_t ah[2][4], al[2][4], bh[2][4], bl[2][4];
#pragma unroll
            for (int mi = 0; mi < 2; mi++) {
                uint32_t ra = (uint32_t)((moff + mi * 16 + arow) * ROWB + kb + ahalf * 16);
                LDSM4(ah[mi], st + OFF_AH + ra);
                LDSM4(al[mi], st + OFF_AL + ra);
            }
#pragma unroll
            for (int ni = 0; ni < 2; ni++) {
                uint32_t rb = (uint32_t)((noff + ni * 16 + brow) * ROWB + kb + bkh * 16);
                LDSM4(bh[ni], st + OFF_BH + rb);
                LDSM4(bl[ni], st + OFF_BL + rb);
            }
#pragma unroll
            for (int mi = 0; mi < 2; mi++)
#pragma unroll
                for (int nj = 0; nj < 4; nj++) {
                    const int L = nj >> 1, p = (nj & 1) * 2;
                    MMA(d[mi][nj], ah[mi], bh[L][p], bh[L][p + 1]);
                    MMA(d[mi][nj], ah[mi], bl[L][p], bl[L][p + 1]);
                    MMA(d[mi][nj], al[mi], bh[L][p], bh[L][p + 1]);
                }
        }
        __syncthreads();
        if (s + NSTAGE < NC) issue(s + NSTAGE);
        cpcommit();
    }

    // ---------------- epilogue: transpose via SMEM, fuse activation ----------
    float* cs = (float*)smem;                   // [64 tokens][132]
    const int rr = lane >> 2, cc = (lane & 3) * 2;
#pragma unroll
    for (int mi = 0; mi < 2; mi++)
#pragma unroll
        for (int nj = 0; nj < 4; nj++) {
            int m = moff + mi * 16 + rr;
            int n = noff + nj * 8 + cc;
            cs[n * 132 + m]           = d[mi][nj][0];
            cs[(n + 1) * 132 + m]     = d[mi][nj][1];
            cs[n * 132 + m + 8]       = d[mi][nj][2];
            cs[(n + 1) * 132 + m + 8] = d[mi][nj][3];
        }
    __syncthreads();

    const int b = t >> 2, j0 = (t & 3) * 32;
    if (mode == 0) {
        float* dst = outf + (size_t)(nbase + b) * ldc + fbase + j0;
        if (bias) {
            const float* bp = bias + fbase + j0;
#pragma unroll 8
            for (int j = 0; j < 32; j++) dst[j] = cs[b * 132 + j0 + j] + bp[j];
        } else {
#pragma unroll 8
            for (int j = 0; j < 32; j++) dst[j] = cs[b * 132 + j0 + j];
        }
    } else if (mode == 1) {
        bf* dh = outh + (size_t)(nbase + b) * ldc + fbase + j0;
        bf* dl = outl + (size_t)(nbase + b) * ldc + fbase + j0;
        const float* bp = bias + fbase + j0;
#pragma unroll 8
        for (int j = 0; j < 32; j++) {
            float v = fmaxf(cs[b * 132 + j0 + j] + bp[j], 0.f);
            bf hi = __float2bfloat16(v);
            dh[j] = hi;
            dl[j] = __float2bfloat16(v - __bfloat162float(hi));
        }
    } else {
        float* dst = outf + (size_t)(nbase + b) * ldc + fbase + j0;
        const float* bp = bias + fbase + j0;
#pragma unroll 8
        for (int j = 0; j < 32; j++) {
            float v = cs[b * 132 + j0 + j] + bp[j];
            dst[j] = 1.f / (1.f + __expf(-v));
        }
    }
}

// fp32 -> (hi, lo) bf16 split
__global__ void split_kernel(const float* __restrict__ src, bf* __restrict__ h,
                             bf* __restrict__ l, int n)
{
    for (int i = blockIdx.x * 256 + threadIdx.x; i < n; i += gridDim.x * 256) {
        float v = src[i];
        bf hi = __float2bfloat16(v);
        h[i] = hi;
        l[i] = __float2bfloat16(v - __bfloat162float(hi));
    }
}

// LSTM pointwise: g = gates0 + gates1 (bias already in gates0)
__global__ void lstm_pw(const float* __restrict__ g0, const float* __restrict__ g1,
                        float* __restrict__ c, bf* __restrict__ hh, bf* __restrict__ hl)
{
    int idx = blockIdx.x * 256 + threadIdx.x;        // 0..131071
    int b = idx >> 11, j = idx & 2047;
    size_t base = (size_t)b * 8192 + j;
    float vi = g0[base]        + g1[base];
    float vf = g0[base + 2048] + g1[base + 2048];
    float vg = g0[base + 4096] + g1[base + 4096];
    float vo = g0[base + 6144] + g1[base + 6144];
    float si = 1.f / (1.f + __expf(-vi));
    float sf = 1.f / (1.f + __expf(-vf));
    float so = 1.f / (1.f + __expf(-vo));
    float c2 = sf * c[idx] + si * tanhf(vg);
    float h2 = so * tanhf(c2);
    c[idx] = c2;
    bf hi = __float2bfloat16(h2);
    hh[idx] = hi;
    hl[idx] = __float2bfloat16(h2 - __bfloat162float(hi));
}

extern "C" void kernel_launch(void* const* d_in, const int* in_sizes, int n_in,
                              void* d_out, int out_size)
{
    const float* x        = (const float*)d_in[0];
    const float* fc_en1_w = (const float*)d_in[1];
    const float* fc_en1_b = (const float*)d_in[2];
    const float* fc_en2_w = (const float*)d_in[3];
    const float* fc_en2_b = (const float*)d_in[4];
    const float* en_wih   = (const float*)d_in[5];
    const float* en_whh   = (const float*)d_in[6];
    const float* en_b     = (const float*)d_in[7];
    const float* de_wih   = (const float*)d_in[8];
    const float* de_whh   = (const float*)d_in[9];
    const float* de_b     = (const float*)d_in[10];
    const float* fc_de1_w = (const float*)d_in[11];
    const float* fc_de1_b = (const float*)d_in[12];
    const float* fc_de2_w = (const float*)d_in[13];
    const float* fc_de2_b = (const float*)d_in[14];
    float* out = (float*)d_out;

    bf *ewih_h, *ewih_l, *ewhh_h, *ewhh_l, *dwih_h, *dwih_l, *dwhh_h, *dwhh_l;
    bf *fc1h, *fc1l, *fc2h, *fc2l, *fd1h, *fd1l, *fd2h, *fd2l;
    bf *xh, *xl, *f1ah, *f1al, *f2ah, *f2al, *d1ah, *d1al, *hah, *hal, *zero;
    float *gates0, *gates1, *c;
    cudaGetSymbolAddress((void**)&ewih_h, g_ewih_h); cudaGetSymbolAddress((void**)&ewih_l, g_ewih_l);
    cudaGetSymbolAddress((void**)&ewhh_h, g_ewhh_h); cudaGetSymbolAddress((void**)&ewhh_l, g_ewhh_l);
    cudaGetSymbolAddress((void**)&dwih_h, g_dwih_h); cudaGetSymbolAddress((void**)&dwih_l, g_dwih_l);
    cudaGetSymbolAddress((void**)&dwhh_h, g_dwhh_h); cudaGetSymbolAddress((void**)&dwhh_l, g_dwhh_l);
    cudaGetSymbolAddress((void**)&fc1h, g_fc1w_h);   cudaGetSymbolAddress((void**)&fc1l, g_fc1w_l);
    cudaGetSymbolAddress((void**)&fc2h, g_fc2w_h);   cudaGetSymbolAddress((void**)&fc2l, g_fc2w_l);
    cudaGetSymbolAddress((void**)&fd1h, g_fd1w_h);   cudaGetSymbolAddress((void**)&fd1l, g_fd1w_l);
    cudaGetSymbolAddress((void**)&fd2h, g_fd2w_h);   cudaGetSymbolAddress((void**)&fd2l, g_fd2w_l);
    cudaGetSymbolAddress((void**)&xh, g_xh);         cudaGetSymbolAddress((void**)&xl, g_xl);
    cudaGetSymbolAddress((void**)&f1ah, g_f1a_h);    cudaGetSymbolAddress((void**)&f1al, g_f1a_l);
    cudaGetSymbolAddress((void**)&f2ah, g_f2a_h);    cudaGetSymbolAddress((void**)&f2al, g_f2a_l);
    cudaGetSymbolAddress((void**)&d1ah, g_d1a_h);    cudaGetSymbolAddress((void**)&d1al, g_d1a_l);
    cudaGetSymbolAddress((void**)&hah, g_ha_h);      cudaGetSymbolAddress((void**)&hal, g_ha_l);
    cudaGetSymbolAddress((void**)&zero, g_zero);
    cudaGetSymbolAddress((void**)&gates0, g_gates0); cudaGetSymbolAddress((void**)&gates1, g_gates1);
    cudaGetSymbolAddress((void**)&c, g_c);

    cudaFuncSetAttribute(gemm_ms, cudaFuncAttributeMaxDynamicSharedMemorySize, SMEM_SZ);

    const int HB = 131072;  // 64*2048 elements

    // ---- one-time splits (re-run each call; deterministic) ----
    split_kernel<<<2048, 256>>>(en_wih,   ewih_h, ewih_l, 3 * LWN);
    split_kernel<<<2048, 256>>>(en_whh,   ewhh_h, ewhh_l, 3 * LWN);
    split_kernel<<<2048, 256>>>(de_wih,   dwih_h, dwih_l, 3 * LWN);
    split_kernel<<<2048, 256>>>(de_whh,   dwhh_h, dwhh_l, 3 * LWN);
    split_kernel<<<2048, 256>>>(fc_en1_w, fc1h, fc1l, 4194304);
    split_kernel<<<2048, 256>>>(fc_en2_w, fc2h, fc2l, 2097152);
    split_kernel<<<2048, 256>>>(fc_de1_w, fd1h, fd1l, 2097152);
    split_kernel<<<2048, 256>>>(fc_de2_w, fd2h, fd2l, 4194304);
    split_kernel<<<2048, 256>>>(x, xh, xl, 4194304);

    cudaMemsetAsync(hah,  0, 3 * HB * sizeof(bf));
    cudaMemsetAsync(hal,  0, 3 * HB * sizeof(bf));
    cudaMemsetAsync(c,    0, 3 * HB * sizeof(float));
    cudaMemsetAsync(zero, 0, HB * sizeof(bf));

    // ---- encoder FCs batched over all 16 steps ----
    gemm_ms<<<dim3(8, 16), 256, SMEM_SZ>>>(fc1h, fc1l, xh, xl, fc_en1_b, nullptr,
        nullptr, nullptr, nullptr, nullptr, nullptr, nullptr,
        f1ah, f1al, 4096, 1024, 1, 0);
    gemm_ms<<<dim3(16, 16), 256, SMEM_SZ>>>(fc2h, fc2l, f1ah, f1al, fc_en2_b, nullptr,
        nullptr, nullptr, nullptr, nullptr, nullptr, nullptr,
        f2ah, f2al, 1024, 2048, 1, 0);

    // ---- encoder LSTM ----
    for (int t = 0; t < 16; t++) {
        for (int l = 0; l < 3; l++) {
            const bf* ih = (l == 0) ? (f2ah + t * HB) : (hah + (l - 1) * HB);
            const bf* il = (l == 0) ? (f2al + t * HB) : (hal + (l - 1) * HB);
            gemm_ms<<<dim3(64, 2), 256, SMEM_SZ>>>(
                ewih_h + (size_t)l * LWN, ewih_l + (size_t)l * LWN, ih, il,
                en_b + l * 8192, gates0,
                ewhh_h + (size_t)l * LWN, ewhh_l + (size_t)l * LWN,
                hah + l * HB, hal + l * HB, nullptr, gates1,
                nullptr, nullptr, 2048, 8192, 0, 1);
            lstm_pw<<<512, 256>>>(gates0, gates1, c + l * HB, hah + l * HB, hal + l * HB);
        }
    }

    // ---- decoder init: h_d0 = h_e2, rest zero ----
    cudaMemcpyAsync(hah, hah + 2 * HB, HB * sizeof(bf), cudaMemcpyDeviceToDevice);
    cudaMemcpyAsync(hal, hal + 2 * HB, HB * sizeof(bf), cudaMemcpyDeviceToDevice);
    cudaMemsetAsync(hah + HB, 0, 2 * HB * sizeof(bf));
    cudaMemsetAsync(hal + HB, 0, 2 * HB * sizeof(bf));
    cudaMemsetAsync(c, 0, 3 * HB * sizeof(float));

    // ---- decoder ----
    for (int t = 0; t < 16; t++) {
        for (int l = 0; l < 3; l++) {
            const bf* ih = (l == 0) ? ((t == 0) ? zero : (hah + 2 * HB)) : (hah + (l - 1) * HB);
            const bf* il = (l == 0) ? ((t == 0) ? zero : (hal + 2 * HB)) : (hal + (l - 1) * HB);
            gemm_ms<<<dim3(64, 2), 256, SMEM_SZ>>>(
                dwih_h + (size_t)l * LWN, dwih_l + (size_t)l * LWN, ih, il,
                de_b + l * 8192, gates0,
                dwhh_h + (size_t)l * LWN, dwhh_l + (size_t)l * LWN,
                hah + l * HB, hal + l * HB, nullptr, gates1,
                nullptr, nullptr, 2048, 8192, 0, 1);
            lstm_pw<<<512, 256>>>(gates0, gates1, c + l * HB, hah + l * HB, hal + l * HB);
        }
        gemm_ms<<<dim3(8, 1), 256, SMEM_SZ>>>(fd1h, fd1l, hah + 2 * HB, hal + 2 * HB,
            fc_de1_b, nullptr, nullptr, nullptr, nullptr, nullptr, nullptr, nullptr,
            d1ah, d1al, 2048, 1024, 1, 0);
        gemm_ms<<<dim3(32, 1), 256, SMEM_SZ>>>(fd2h, fd2l, d1ah, d1al,
            fc_de2_b, out + (size_t)t * 262144, nullptr, nullptr, nullptr, nullptr,
            nullptr, nullptr, nullptr, nullptr, 1024, 4096, 2, 0);
    }
}

// round 5
// speedup vs baseline: 3.0958x; 1.0735x over previous
#include <cuda_runtime.h>
#include <cuda_bf16.h>
#include <cstdint>
#include <cstddef>

typedef __nv_bfloat16 bf;

// ---------------- tile constants ----------------
#define TM    128
#define TN    64
#define ROWB  144                 // padded SMEM row (72 bf16) -> conflict-free ldmatrix
#define OFF_AH 0
#define OFF_AL 18432
#define OFF_BH 36864
#define OFF_BL 46080
#define STAGE  55296
#define SMEM_SZ (2 * STAGE)       // 110592 B -> 2 CTAs/SM

// ---------------- asm helpers ----------------
__device__ __forceinline__ void cpa(uint32_t d, const void* s) {
    asm volatile("cp.async.cg.shared.global [%0], [%1], 16;" :: "r"(d), "l"(s));
}
__device__ __forceinline__ void cpcommit() {
    asm volatile("cp.async.commit_group;" ::: "memory");
}
template <int N> __device__ __forceinline__ void cpwait() {
    asm volatile("cp.async.wait_group %0;" :: "n"(N) : "memory");
}
#define LDSM4(R, addr) \
    asm volatile("ldmatrix.sync.aligned.m8n8.x4.shared.b16 {%0,%1,%2,%3}, [%4];" \
        : "=r"((R)[0]), "=r"((R)[1]), "=r"((R)[2]), "=r"((R)[3]) : "r"(addr))
#define MMA(D, A, b0, b1) \
    asm volatile("mma.sync.aligned.m16n8k16.row.col.f32.bf16.bf16.f32 " \
        "{%0,%1,%2,%3}, {%4,%5,%6,%7}, {%8,%9}, {%0,%1,%2,%3};" \
        : "+f"((D)[0]), "+f"((D)[1]), "+f"((D)[2]), "+f"((D)[3]) \
        : "r"((A)[0]), "r"((A)[1]), "r"((A)[2]), "r"((A)[3]), "r"(b0), "r"(b1))

// ---------------- scratch ----------------
#define LWN 16777216               // 8192*2048
__device__ bf g_ewih_h[3*LWN], g_ewih_l[3*LWN];
__device__ bf g_ewhh_h[3*LWN], g_ewhh_l[3*LWN];
__device__ bf g_dwih_h[3*LWN], g_dwih_l[3*LWN];
__device__ bf g_dwhh_h[3*LWN], g_dwhh_l[3*LWN];
__device__ bf g_fc1w_h[4194304], g_fc1w_l[4194304];
__device__ bf g_fc2w_h[2097152], g_fc2w_l[2097152];
__device__ bf g_fd1w_h[2097152], g_fd1w_l[2097152];
__device__ bf g_fd2w_h[4194304], g_fd2w_l[4194304];
__device__ bf g_xh[4194304],    g_xl[4194304];
__device__ bf g_f1a_h[1048576], g_f1a_l[1048576];
__device__ bf g_f2a_h[2097152], g_f2a_l[2097152];
__device__ bf g_d1a_h[65536],   g_d1a_l[65536];
__device__ bf g_ha_h[393216],   g_ha_l[393216];       // 3 x [64,2048] batch-major
__device__ bf g_zero[131072];
__device__ float g_parts[4 * 524288];                 // 4 x [8192,64] f-major partials
__device__ float g_c[393216];                         // 3 x [2048,64] f-major

// ===========================================================================
// Fused split prepass: fp32 -> (hi,lo) bf16 for all 9 tensors, one launch.
// ===========================================================================
struct SplitArgs {
    const float* s[9];
    bf* h[9];
    bf* l[9];
    long off4[10];   // prefix sums in float4 units
};

__global__ void __launch_bounds__(256) split_all(SplitArgs a)
{
    const long total = a.off4[9];
    for (long v = (long)blockIdx.x * 256 + threadIdx.x; v < total;
         v += (long)gridDim.x * 256) {
        int seg = 0;
#pragma unroll
        for (int i = 0; i < 8; i++) seg += (v >= a.off4[i + 1]) ? 1 : 0;
        long e = (v - a.off4[seg]) * 4;
        float4 x = *(const float4*)(a.s[seg] + e);
        bf h0 = __float2bfloat16(x.x), h1 = __float2bfloat16(x.y);
        bf h2 = __float2bfloat16(x.z), h3 = __float2bfloat16(x.w);
        bf l0 = __float2bfloat16(x.x - __bfloat162float(h0));
        bf l1 = __float2bfloat16(x.y - __bfloat162float(h1));
        bf l2 = __float2bfloat16(x.z - __bfloat162float(h2));
        bf l3 = __float2bfloat16(x.w - __bfloat162float(h3));
        uint2 ph, pl;
        ph.x = (uint32_t)*(uint16_t*)&h0 | ((uint32_t)*(uint16_t*)&h1 << 16);
        ph.y = (uint32_t)*(uint16_t*)&h2 | ((uint32_t)*(uint16_t*)&h3 << 16);
        pl.x = (uint32_t)*(uint16_t*)&l0 | ((uint32_t)*(uint16_t*)&l1 << 16);
        pl.y = (uint32_t)*(uint16_t*)&l2 | ((uint32_t)*(uint16_t*)&l3 << 16);
        *(uint2*)(a.h[seg] + e) = ph;
        *(uint2*)(a.l[seg] + e) = pl;
    }
}

// ===========================================================================
// Split-precision bf16 mma.sync GEMM, 2-stage cp.async pipeline, 2 CTAs/SM.
//   D[f, b] = sum_k W[f,k] * act[b,k]   (3-term hi/lo)
// dual=1: grid.y in 0..3 -> (matrix = y>>1 ih/hh, K-half = y&1);
//         partial fp32 written f-major to outf + y*524288 (no bias).
// dual=0: grid.y = token tile; modes: 0 fp32+bias, 1 relu+split, 2 sigmoid.
// ===========================================================================
__global__ void __launch_bounds__(256, 2)
gemm_ms(const bf* __restrict__ Ah0, const bf* __restrict__ Al0,
        const bf* __restrict__ Bh0, const bf* __restrict__ Bl0,
        const bf* __restrict__ Ah1, const bf* __restrict__ Al1,
        const bf* __restrict__ Bh1, const bf* __restrict__ Bl1,
        const float* __restrict__ bias,
        float* __restrict__ outf, bf* __restrict__ outh, bf* __restrict__ outl,
        int K, int Keff, int ldc, int mode, int dual)
{
    extern __shared__ char smem[];
    const uint32_t sb = (uint32_t)__cvta_generic_to_shared(smem);
    const int t = threadIdx.x;
    const int fbase = blockIdx.x * TM;

    const bf *Ah, *Al, *Bh, *Bl;
    int nbase = 0, koffs = 0, part = 0;
    if (dual) {
        part = blockIdx.y;
        const int mat = part >> 1;
        koffs = (part & 1) * Keff;
        if (mat) { Ah = Ah1; Al = Al1; Bh = Bh1; Bl = Bl1; }
        else     { Ah = Ah0; Al = Al0; Bh = Bh0; Bl = Bl0; }
    } else {
        Ah = Ah0; Al = Al0; Bh = Bh0; Bl = Bl0;
        nbase = blockIdx.y * TN;
    }
    const bf* aH = Ah + (size_t)fbase * K + koffs;
    const bf* aL = Al + (size_t)fbase * K + koffs;
    const bf* bH = Bh + (size_t)nbase * K + koffs;
    const bf* bL = Bl + (size_t)nbase * K + koffs;
    const int NC = Keff >> 6;

    const int r0 = t >> 3, seg = t & 7;
    auto issue = [&](int chunk) {
        const uint32_t st = sb + (chunk & 1) * STAGE;
        const int koff = (chunk << 6) + seg * 8;
#pragma unroll
        for (int i = 0; i < 4; i++) {
            int row = r0 + i * 32;
            uint32_t d = st + row * ROWB + seg * 16;
            cpa(d + OFF_AH, aH + (size_t)row * K + koff);
            cpa(d + OFF_AL, aL + (size_t)row * K + koff);
        }
#pragma unroll
        for (int i = 0; i < 2; i++) {
            int row = r0 + i * 32;
            uint32_t d = st + row * ROWB + seg * 16;
            cpa(d + OFF_BH, bH + (size_t)row * K + koff);
            cpa(d + OFF_BL, bL + (size_t)row * K + koff);
        }
    };

    issue(0); cpcommit();
    issue(1); cpcommit();

    const int w = t >> 5, lane = t & 31;
    const int moff = (w & 3) * 32;
    const int noff = (w >> 2) * 32;
    const int arow = lane & 15, ahalf = lane >> 4;
    const int bj = lane >> 3;
    const int brow = ((bj >> 1) * 8) + (lane & 7), bkh = bj & 1;

    float d[2][4][4];
#pragma unroll
    for (int mi = 0; mi < 2; mi++)
#pragma unroll
        for (int nj = 0; nj < 4; nj++)
#pragma unroll
            for (int q = 0; q < 4; q++) d[mi][nj][q] = 0.f;

    for (int s = 0; s < NC; s++) {
        cpwait<1>();
        __syncthreads();
        const uint32_t st = sb + (s & 1) * STAGE;
#pragma unroll
        for (int k16 = 0; k16 < 4; k16++) {
            const int kb = k16 * 32;
            uint32_t ah[2][4], al[2][4], bh[2][4], bl[2][4];
#pragma unroll
            for (int mi = 0; mi < 2; mi++) {
                uint32_t ra = (uint32_t)((moff + mi * 16 + arow) * ROWB + kb + ahalf * 16);
                LDSM4(ah[mi], st + OFF_AH + ra);
                LDSM4(al[mi], st + OFF_AL + ra);
            }
#pragma unroll
            for (int ni = 0; ni < 2; ni++) {
                uint32_t rb = (uint32_t)((noff + ni * 16 + brow) * ROWB + kb + bkh * 16);
                LDSM4(bh[ni], st + OFF_BH + rb);
                LDSM4(bl[ni], st + OFF_BL + rb);
            }
#pragma unroll
            for (int mi = 0; mi < 2; mi++)
#pragma unroll
                for (int nj = 0; nj < 4; nj++) {
                    const int L = nj >> 1, p = (nj & 1) * 2;
                    MMA(d[mi][nj], ah[mi], bh[L][p], bh[L][p + 1]);
                    MMA(d[mi][nj], ah[mi], bl[L][p], bl[L][p + 1]);
                    MMA(d[mi][nj], al[mi], bh[L][p], bh[L][p + 1]);
                }
        }
        __syncthreads();
        if (s + 2 < NC) issue(s + 2);
        cpcommit();
    }

    const int rr = lane >> 2, cc = (lane & 3) * 2;

    if (dual) {
        // direct f-major partial store: parts[part][(fbase+m)*64 + n]
        float* po = outf + (size_t)part * 524288;
#pragma unroll
        for (int mi = 0; mi < 2; mi++)
#pragma unroll
            for (int nj = 0; nj < 4; nj++) {
                int m = moff + mi * 16 + rr;
                int n = noff + nj * 8 + cc;
                *(float2*)(po + (size_t)(fbase + m) * 64 + n) =
                    make_float2(d[mi][nj][0], d[mi][nj][1]);
                *(float2*)(po + (size_t)(fbase + m + 8) * 64 + n) =
                    make_float2(d[mi][nj][2], d[mi][nj][3]);
            }
        return;
    }

    // non-dual epilogue: transpose via SMEM to batch-major, fuse activation
    float* cs = (float*)smem;                   // [64][132]
#pragma unroll
    for (int mi = 0; mi < 2; mi++)
#pragma unroll
        for (int nj = 0; nj < 4; nj++) {
            int m = moff + mi * 16 + rr;
            int n = noff + nj * 8 + cc;
            cs[n * 132 + m]           = d[mi][nj][0];
            cs[(n + 1) * 132 + m]     = d[mi][nj][1];
            cs[n * 132 + m + 8]       = d[mi][nj][2];
            cs[(n + 1) * 132 + m + 8] = d[mi][nj][3];
        }
    __syncthreads();

    const int b = t >> 2, j0 = (t & 3) * 32;
    const float* bp = bias + fbase + j0;
    if (mode == 0) {
        float* dst = outf + (size_t)(nbase + b) * ldc + fbase + j0;
#pragma unroll 8
        for (int j = 0; j < 32; j++) dst[j] = cs[b * 132 + j0 + j] + bp[j];
    } else if (mode == 1) {
        bf* dh = outh + (size_t)(nbase + b) * ldc + fbase + j0;
        bf* dl = outl + (size_t)(nbase + b) * ldc + fbase + j0;
#pragma unroll 8
        for (int j = 0; j < 32; j++) {
            float v = fmaxf(cs[b * 132 + j0 + j] + bp[j], 0.f);
            bf hi = __float2bfloat16(v);
            dh[j] = hi;
            dl[j] = __float2bfloat16(v - __bfloat162float(hi));
        }
    } else {
        float* dst = outf + (size_t)(nbase + b) * ldc + fbase + j0;
#pragma unroll 8
        for (int j = 0; j < 32; j++) {
            float v = cs[b * 132 + j0 + j] + bp[j];
            dst[j] = 1.f / (1.f + __expf(-v));
        }
    }
}

// ===========================================================================
// LSTM pointwise: sum 4 f-major partials + bias, update f-major c,
// write batch-major h (hi/lo) via smem transpose. grid 64 x 256.
// ===========================================================================
__global__ void __launch_bounds__(256) lstm_pw(
    const float* __restrict__ parts, const float* __restrict__ bias,
    float* __restrict__ c, bf* __restrict__ hh, bf* __restrict__ hl)
{
    __shared__ bf shh[32][65], shl[32][65];
    const int t = threadIdx.x;
    const int jbase = blockIdx.x * 32;
    const int b = t & 63, jo = t >> 6;          // jo in 0..3
    const float* p0 = parts;
    const float* p1 = parts + 524288;
    const float* p2 = parts + 1048576;
    const float* p3 = parts + 1572864;

#pragma unroll
    for (int it = 0; it < 8; it++) {
        const int jl = it * 4 + jo;
        const int j = jbase + jl;
        float g[4];
#pragma unroll
        for (int gt = 0; gt < 4; gt++) {
            size_t off = (size_t)(gt * 2048 + j) * 64 + b;
            g[gt] = p0[off] + p1[off] + p2[off] + p3[off] + bias[gt * 2048 + j];
        }
        float si = 1.f / (1.f + __expf(-g[0]));
        float sf = 1.f / (1.f + __expf(-g[1]));
        float so = 1.f / (1.f + __expf(-g[3]));
        size_t ci = (size_t)j * 64 + b;
        float c2 = sf * c[ci] + si * tanhf(g[2]);
        float h2 = so * tanhf(c2);
        c[ci] = c2;
        bf hi = __float2bfloat16(h2);
        shh[jl][b] = hi;
        shl[jl][b] = __float2bfloat16(h2 - __bfloat162float(hi));
    }
    __syncthreads();
    // write out batch-major: thread -> row bo = t>>2, 8 j's
    const int bo = t >> 2, js = (t & 3) * 8;
    bf th[8], tl[8];
#pragma unroll
    for (int k = 0; k < 8; k++) { th[k] = shh[js + k][bo]; tl[k] = shl[js + k][bo]; }
    *(uint4*)(hh + (size_t)bo * 2048 + jbase + js) = *(uint4*)th;
    *(uint4*)(hl + (size_t)bo * 2048 + jbase + js) = *(uint4*)tl;
}

extern "C" void kernel_launch(void* const* d_in, const int* in_sizes, int n_in,
                              void* d_out, int out_size)
{
    const float* x        = (const float*)d_in[0];
    const float* fc_en1_w = (const float*)d_in[1];
    const float* fc_en1_b = (const float*)d_in[2];
    const float* fc_en2_w = (const float*)d_in[3];
    const float* fc_en2_b = (const float*)d_in[4];
    const float* en_wih   = (const float*)d_in[5];
    const float* en_whh   = (const float*)d_in[6];
    const float* en_b     = (const float*)d_in[7];
    const float* de_wih   = (const float*)d_in[8];
    const float* de_whh   = (const float*)d_in[9];
    const float* de_b     = (const float*)d_in[10];
    const float* fc_de1_w = (const float*)d_in[11];
    const float* fc_de1_b = (const float*)d_in[12];
    const float* fc_de2_w = (const float*)d_in[13];
    const float* fc_de2_b = (const float*)d_in[14];
    float* out = (float*)d_out;

    bf *ewih_h, *ewih_l, *ewhh_h, *ewhh_l, *dwih_h, *dwih_l, *dwhh_h, *dwhh_l;
    bf *fc1h, *fc1l, *fc2h, *fc2l, *fd1h, *fd1l, *fd2h, *fd2l;
    bf *xh, *xl, *f1ah, *f1al, *f2ah, *f2al, *d1ah, *d1al, *hah, *hal, *zero;
    float *parts, *c;
    cudaGetSymbolAddress((void**)&ewih_h, g_ewih_h); cudaGetSymbolAddress((void**)&ewih_l, g_ewih_l);
    cudaGetSymbolAddress((void**)&ewhh_h, g_ewhh_h); cudaGetSymbolAddress((void**)&ewhh_l, g_ewhh_l);
    cudaGetSymbolAddress((void**)&dwih_h, g_dwih_h); cudaGetSymbolAddress((void**)&dwih_l, g_dwih_l);
    cudaGetSymbolAddress((void**)&dwhh_h, g_dwhh_h); cudaGetSymbolAddress((void**)&dwhh_l, g_dwhh_l);
    cudaGetSymbolAddress((void**)&fc1h, g_fc1w_h);   cudaGetSymbolAddress((void**)&fc1l, g_fc1w_l);
    cudaGetSymbolAddress((void**)&fc2h, g_fc2w_h);   cudaGetSymbolAddress((void**)&fc2l, g_fc2w_l);
    cudaGetSymbolAddress((void**)&fd1h, g_fd1w_h);   cudaGetSymbolAddress((void**)&fd1l, g_fd1w_l);
    cudaGetSymbolAddress((void**)&fd2h, g_fd2w_h);   cudaGetSymbolAddress((void**)&fd2l, g_fd2w_l);
    cudaGetSymbolAddress((void**)&xh, g_xh);         cudaGetSymbolAddress((void**)&xl, g_xl);
    cudaGetSymbolAddress((void**)&f1ah, g_f1a_h);    cudaGetSymbolAddress((void**)&f1al, g_f1a_l);
    cudaGetSymbolAddress((void**)&f2ah, g_f2a_h);    cudaGetSymbolAddress((void**)&f2al, g_f2a_l);
    cudaGetSymbolAddress((void**)&d1ah, g_d1a_h);    cudaGetSymbolAddress((void**)&d1al, g_d1a_l);
    cudaGetSymbolAddress((void**)&hah, g_ha_h);      cudaGetSymbolAddress((void**)&hal, g_ha_l);
    cudaGetSymbolAddress((void**)&zero, g_zero);
    cudaGetSymbolAddress((void**)&parts, g_parts);   cudaGetSymbolAddress((void**)&c, g_c);

    cudaFuncSetAttribute(gemm_ms, cudaFuncAttributeMaxDynamicSharedMemorySize, SMEM_SZ);

    const int HB = 131072;

    // ---- fused split prepass (launch #1) ----
    {
        SplitArgs a;
        const float* srcs[9] = {en_wih, en_whh, de_wih, de_whh, fc_en1_w,
                                fc_en2_w, fc_de1_w, fc_de2_w, x};
        bf* hs[9] = {ewih_h, ewhh_h, dwih_h, dwhh_h, fc1h, fc2h, fd1h, fd2h, xh};
        bf* ls[9] = {ewih_l, ewhh_l, dwih_l, dwhh_l, fc1l, fc2l, fd1l, fd2l, xl};
        long ns[9] = {3L*LWN, 3L*LWN, 3L*LWN, 3L*LWN, 4194304, 2097152,
                      2097152, 4194304, 4194304};
        long acc = 0;
        for (int i = 0; i < 9; i++) {
            a.s[i] = srcs[i]; a.h[i] = hs[i]; a.l[i] = ls[i];
            a.off4[i] = acc; acc += ns[i] / 4;
        }
        a.off4[9] = acc;
        split_all<<<2048, 256>>>(a);
    }

    cudaMemsetAsync(hah,  0, 3 * HB * sizeof(bf));
    cudaMemsetAsync(hal,  0, 3 * HB * sizeof(bf));
    cudaMemsetAsync(c,    0, 3 * HB * sizeof(float));
    cudaMemsetAsync(zero, 0, HB * sizeof(bf));

    // ---- encoder FCs batched over all 16 steps ----
    gemm_ms<<<dim3(8, 16), 256, SMEM_SZ>>>(fc1h, fc1l, xh, xl,
        nullptr, nullptr, nullptr, nullptr, fc_en1_b,
        nullptr, f1ah, f1al, 4096, 4096, 1024, 1, 0);
    gemm_ms<<<dim3(16, 16), 256, SMEM_SZ>>>(fc2h, fc2l, f1ah, f1al,
        nullptr, nullptr, nullptr, nullptr, fc_en2_b,
        nullptr, f2ah, f2al, 1024, 1024, 2048, 1, 0);

    // ---- encoder LSTM ----
    for (int t = 0; t < 16; t++) {
        for (int l = 0; l < 3; l++) {
            const bf* ih = (l == 0) ? (f2ah + t * HB) : (hah + (l - 1) * HB);
            const bf* il = (l == 0) ? (f2al + t * HB) : (hal + (l - 1) * HB);
            gemm_ms<<<dim3(64, 4), 256, SMEM_SZ>>>(
                ewih_h + (size_t)l * LWN, ewih_l + (size_t)l * LWN, ih, il,
                ewhh_h + (size_t)l * LWN, ewhh_l + (size_t)l * LWN,
                hah + l * HB, hal + l * HB, nullptr,
                parts, nullptr, nullptr, 2048, 1024, 0, 0, 1);
            lstm_pw<<<64, 256>>>(parts, en_b + l * 8192, c + l * HB,
                                 hah + l * HB, hal + l * HB);
        }
    }

    // ---- decoder init: h_d0 = h_e2, rest zero ----
    cudaMemcpyAsync(hah, hah + 2 * HB, HB * sizeof(bf), cudaMemcpyDeviceToDevice);
    cudaMemcpyAsync(hal, hal + 2 * HB, HB * sizeof(bf), cudaMemcpyDeviceToDevice);
    cudaMemsetAsync(hah + HB, 0, 2 * HB * sizeof(bf));
    cudaMemsetAsync(hal + HB, 0, 2 * HB * sizeof(bf));
    cudaMemsetAsync(c, 0, 3 * HB * sizeof(float));

    // ---- decoder ----
    for (int t = 0; t < 16; t++) {
        for (int l = 0; l < 3; l++) {
            const bf* ih = (l == 0) ? ((t == 0) ? zero : (hah + 2 * HB)) : (hah + (l - 1) * HB);
            const bf* il = (l == 0) ? ((t == 0) ? zero : (hal + 2 * HB)) : (hal + (l - 1) * HB);
            gemm_ms<<<dim3(64, 4), 256, SMEM_SZ>>>(
                dwih_h + (size_t)l * LWN, dwih_l + (size_t)l * LWN, ih, il,
                dwhh_h + (size_t)l * LWN, dwhh_l + (size_t)l * LWN,
                hah + l * HB, hal + l * HB, nullptr,
                parts, nullptr, nullptr, 2048, 1024, 0, 0, 1);
            lstm_pw<<<64, 256>>>(parts, de_b + l * 8192, c + l * HB,
                                 hah + l * HB, hal + l * HB);
        }
        gemm_ms<<<dim3(8, 1), 256, SMEM_SZ>>>(fd1h, fd1l, hah + 2 * HB, hal + 2 * HB,
            nullptr, nullptr, nullptr, nullptr, fc_de1_b,
            nullptr, d1ah, d1al, 2048, 2048, 1024, 1, 0);
        gemm_ms<<<dim3(32, 1), 256, SMEM_SZ>>>(fd2h, fd2l, d1ah, d1al,
            nullptr, nullptr, nullptr, nullptr, fc_de2_b,
            out + (size_t)t * 262144, nullptr, nullptr, 1024, 1024, 4096, 2, 0);
    }
}

// round 6
// speedup vs baseline: 3.3929x; 1.0960x over previous
#include <cuda_runtime.h>
#include <cuda_bf16.h>
#include <cstdint>
#include <cstddef>

typedef __nv_bfloat16 bf;

// ---------------- tile constants ----------------
#define TM    64
#define TN    64
#define ROWB  144                 // padded SMEM row (72 bf16) -> conflict-free ldmatrix
#define OFF_AH 0
#define OFF_AL 9216
#define OFF_BH 18432
#define OFF_BL 27648
#define STAGE  36864
#define SMEM_SZ (3 * STAGE)       // 110592 B -> 2 CTAs/SM

// ---------------- asm helpers ----------------
__device__ __forceinline__ void cpa(uint32_t d, const void* s) {
    asm volatile("cp.async.cg.shared.global [%0], [%1], 16;" :: "r"(d), "l"(s));
}
__device__ __forceinline__ void cpcommit() {
    asm volatile("cp.async.commit_group;" ::: "memory");
}
template <int N> __device__ __forceinline__ void cpwait() {
    asm volatile("cp.async.wait_group %0;" :: "n"(N) : "memory");
}
#define LDSM4(R, addr) \
    asm volatile("ldmatrix.sync.aligned.m8n8.x4.shared.b16 {%0,%1,%2,%3}, [%4];" \
        : "=r"((R)[0]), "=r"((R)[1]), "=r"((R)[2]), "=r"((R)[3]) : "r"(addr))
#define MMA(D, A, b0, b1) \
    asm volatile("mma.sync.aligned.m16n8k16.row.col.f32.bf16.bf16.f32 " \
        "{%0,%1,%2,%3}, {%4,%5,%6,%7}, {%8,%9}, {%0,%1,%2,%3};" \
        : "+f"((D)[0]), "+f"((D)[1]), "+f"((D)[2]), "+f"((D)[3]) \
        : "r"((A)[0]), "r"((A)[1]), "r"((A)[2]), "r"((A)[3]), "r"(b0), "r"(b1))

// ---------------- scratch ----------------
#define LWN 16777216               // 8192*2048
__device__ bf g_ewih_h[3*LWN], g_ewih_l[3*LWN];
__device__ bf g_ewhh_h[3*LWN], g_ewhh_l[3*LWN];
__device__ bf g_dwih_h[3*LWN], g_dwih_l[3*LWN];
__device__ bf g_dwhh_h[3*LWN], g_dwhh_l[3*LWN];
__device__ bf g_fc1w_h[4194304], g_fc1w_l[4194304];
__device__ bf g_fc2w_h[2097152], g_fc2w_l[2097152];
__device__ bf g_fd1w_h[2097152], g_fd1w_l[2097152];
__device__ bf g_fd2w_h[4194304], g_fd2w_l[4194304];
__device__ bf g_xh[4194304],    g_xl[4194304];
__device__ bf g_f1a_h[1048576], g_f1a_l[1048576];
__device__ bf g_f2a_h[2097152], g_f2a_l[2097152];
__device__ bf g_d1a_h[65536],   g_d1a_l[65536];
__device__ bf g_ha_h[393216],   g_ha_l[393216];       // 3 x [64,2048] batch-major
__device__ bf g_zero[131072];
__device__ float g_parts[2 * 524288];                 // 2 x [8192,64] f-major partials
__device__ float g_pre[16 * 524288];                  // enc-l0 pre-gates, f-major per step
__device__ float g_c[393216];                         // 3 x [2048,64] f-major

// ===========================================================================
// Fused split prepass
// ===========================================================================
struct SplitArgs {
    const float* s[9];
    bf* h[9];
    bf* l[9];
    long off4[10];
};

__global__ void __launch_bounds__(256) split_all(SplitArgs a)
{
    const long total = a.off4[9];
    for (long v = (long)blockIdx.x * 256 + threadIdx.x; v < total;
         v += (long)gridDim.x * 256) {
        int seg = 0;
#pragma unroll
        for (int i = 0; i < 8; i++) seg += (v >= a.off4[i + 1]) ? 1 : 0;
        long e = (v - a.off4[seg]) * 4;
        float4 x = *(const float4*)(a.s[seg] + e);
        bf h0 = __float2bfloat16(x.x), h1 = __float2bfloat16(x.y);
        bf h2 = __float2bfloat16(x.z), h3 = __float2bfloat16(x.w);
        bf l0 = __float2bfloat16(x.x - __bfloat162float(h0));
        bf l1 = __float2bfloat16(x.y - __bfloat162float(h1));
        bf l2 = __float2bfloat16(x.z - __bfloat162float(h2));
        bf l3 = __float2bfloat16(x.w - __bfloat162float(h3));
        uint2 ph, pl;
        ph.x = (uint32_t)*(uint16_t*)&h0 | ((uint32_t)*(uint16_t*)&h1 << 16);
        ph.y = (uint32_t)*(uint16_t*)&h2 | ((uint32_t)*(uint16_t*)&h3 << 16);
        pl.x = (uint32_t)*(uint16_t*)&l0 | ((uint32_t)*(uint16_t*)&l1 << 16);
        pl.y = (uint32_t)*(uint16_t*)&l2 | ((uint32_t)*(uint16_t*)&l3 << 16);
        *(uint2*)(a.h[seg] + e) = ph;
        *(uint2*)(a.l[seg] + e) = pl;
    }
}

// ===========================================================================
// Split-precision bf16 mma.sync GEMM. TM=64, 3-stage pipeline, 1 sync/chunk.
//   D[f, b] = sum_k W[f,k] * act[b,k]   (3-term hi/lo)
// dual=1: grid.y = slot (0/1 operand set), f-major partial to outf+y*524288
// dual=2: grid.y = token tile, f-major store to outf+y*524288 (slot0 ops)
// dual=0: grid.y = token tile; mode 0 fp32+bias, 1 relu+split, 2 sigmoid
// ===========================================================================
__global__ void __launch_bounds__(256, 2)
gemm_ms(const bf* __restrict__ Ah0, const bf* __restrict__ Al0,
        const bf* __restrict__ Bh0, const bf* __restrict__ Bl0,
        const bf* __restrict__ Ah1, const bf* __restrict__ Al1,
        const bf* __restrict__ Bh1, const bf* __restrict__ Bl1,
        const float* __restrict__ bias,
        float* __restrict__ outf, bf* __restrict__ outh, bf* __restrict__ outl,
        int K, int ldc, int mode, int dual)
{
    extern __shared__ char smem[];
    const uint32_t sb = (uint32_t)__cvta_generic_to_shared(smem);
    const int t = threadIdx.x;
    const int fbase = blockIdx.x * TM;

    const bf *Ah, *Al, *Bh, *Bl;
    int nbase = 0;
    if (dual == 1 && blockIdx.y == 1) { Ah = Ah1; Al = Al1; Bh = Bh1; Bl = Bl1; }
    else {
        Ah = Ah0; Al = Al0; Bh = Bh0; Bl = Bl0;
        if (dual != 1) nbase = blockIdx.y * TN;
    }
    const bf* aH = Ah + (size_t)fbase * K;
    const bf* aL = Al + (size_t)fbase * K;
    const bf* bH = Bh + (size_t)nbase * K;
    const bf* bL = Bl + (size_t)nbase * K;
    const int NC = K >> 6;

    const int r0 = t >> 3, seg = t & 7;
    auto issue = [&](int chunk) {
        const uint32_t st = sb + (chunk % 3) * STAGE;
        const int koff = (chunk << 6) + seg * 8;
#pragma unroll
        for (int i = 0; i < 2; i++) {
            int row = r0 + i * 32;
            uint32_t d = st + row * ROWB + seg * 16;
            cpa(d + OFF_AH, aH + (size_t)row * K + koff);
            cpa(d + OFF_AL, aL + (size_t)row * K + koff);
            cpa(d + OFF_BH, bH + (size_t)row * K + koff);
            cpa(d + OFF_BL, bL + (size_t)row * K + koff);
        }
    };

    issue(0); cpcommit();
    issue(1); cpcommit();

    const int w = t >> 5, lane = t & 31;
    const int moff = (w & 1) * 32;
    const int noff = (w >> 1) * 16;
    const int arow = lane & 15, ahalf = lane >> 4;
    const int bj = lane >> 3;
    const int brow = ((bj >> 1) * 8) + (lane & 7), bkh = bj & 1;

    float d[2][2][4];
#pragma unroll
    for (int mi = 0; mi < 2; mi++)
#pragma unroll
        for (int nj = 0; nj < 2; nj++)
#pragma unroll
            for (int q = 0; q < 4; q++) d[mi][nj][q] = 0.f;

    for (int s = 0; s < NC; s++) {
        cpwait<1>();
        __syncthreads();
        const uint32_t st = sb + (s % 3) * STAGE;
#pragma unroll
        for (int k16 = 0; k16 < 4; k16++) {
            const int kb = k16 * 32;
            uint32_t ah[2][4], al[2][4], bh[4], bl[4];
#pragma unroll
            for (int mi = 0; mi < 2; mi++) {
                uint32_t ra = (uint32_t)((moff + mi * 16 + arow) * ROWB + kb + ahalf * 16);
                LDSM4(ah[mi], st + OFF_AH + ra);
                LDSM4(al[mi], st + OFF_AL + ra);
            }
            {
                uint32_t rb = (uint32_t)((noff + brow) * ROWB + kb + bkh * 16);
                LDSM4(bh, st + OFF_BH + rb);
                LDSM4(bl, st + OFF_BL + rb);
            }
#pragma unroll
            for (int mi = 0; mi < 2; mi++)
#pragma unroll
                for (int nj = 0; nj < 2; nj++) {
                    const int p = nj * 2;
                    MMA(d[mi][nj], ah[mi], bh[p], bh[p + 1]);
                    MMA(d[mi][nj], ah[mi], bl[p], bl[p + 1]);
                    MMA(d[mi][nj], al[mi], bh[p], bh[p + 1]);
                }
        }
        if (s + 2 < NC) issue(s + 2);
        cpcommit();
    }

    const int rr = lane >> 2, cc = (lane & 3) * 2;

    if (dual) {
        float* po = outf + (size_t)blockIdx.y * 524288;
#pragma unroll
        for (int mi = 0; mi < 2; mi++)
#pragma unroll
            for (int nj = 0; nj < 2; nj++) {
                int m = moff + mi * 16 + rr;
                int n = noff + nj * 8 + cc;
                *(float2*)(po + (size_t)(fbase + m) * 64 + n) =
                    make_float2(d[mi][nj][0], d[mi][nj][1]);
                *(float2*)(po + (size_t)(fbase + m + 8) * 64 + n) =
                    make_float2(d[mi][nj][2], d[mi][nj][3]);
            }
        return;
    }

    // batch-major epilogue with fused activation
    __syncthreads();
    float* cs = (float*)smem;                   // [64][68]
#pragma unroll
    for (int mi = 0; mi < 2; mi++)
#pragma unroll
        for (int nj = 0; nj < 2; nj++) {
            int m = moff + mi * 16 + rr;
            int n = noff + nj * 8 + cc;
            cs[n * 68 + m]           = d[mi][nj][0];
            cs[(n + 1) * 68 + m]     = d[mi][nj][1];
            cs[n * 68 + m + 8]       = d[mi][nj][2];
            cs[(n + 1) * 68 + m + 8] = d[mi][nj][3];
        }
    __syncthreads();

    const int b = t >> 2, j0 = (t & 3) * 16;
    const float* bp = bias + fbase + j0;
    if (mode == 0) {
        float* dst = outf + (size_t)(nbase + b) * ldc + fbase + j0;
#pragma unroll
        for (int j = 0; j < 16; j++) dst[j] = cs[b * 68 + j0 + j] + bp[j];
    } else if (mode == 1) {
        bf* dh = outh + (size_t)(nbase + b) * ldc + fbase + j0;
        bf* dl = outl + (size_t)(nbase + b) * ldc + fbase + j0;
#pragma unroll
        for (int j = 0; j < 16; j++) {
            float v = fmaxf(cs[b * 68 + j0 + j] + bp[j], 0.f);
            bf hi = __float2bfloat16(v);
            dh[j] = hi;
            dl[j] = __float2bfloat16(v - __bfloat162float(hi));
        }
    } else {
        float* dst = outf + (size_t)(nbase + b) * ldc + fbase + j0;
#pragma unroll
        for (int j = 0; j < 16; j++) {
            float v = cs[b * 68 + j0 + j] + bp[j];
            dst[j] = 1.f / (1.f + __expf(-v));
        }
    }
}

// ===========================================================================
// LSTM pointwise: g = p0 + (p1?) + (pre?) + bias  (all f-major [8192,64]);
// update f-major c; write batch-major h (hi/lo) via smem transpose.
// ===========================================================================
__global__ void __launch_bounds__(256) lstm_pw(
    const float* __restrict__ p0, const float* __restrict__ p1,
    const float* __restrict__ pre, const float* __restrict__ bias,
    float* __restrict__ c, bf* __restrict__ hh, bf* __restrict__ hl)
{
    __shared__ bf shh[32][65], shl[32][65];
    const int t = threadIdx.x;
    const int jbase = blockIdx.x * 32;
    const int b = t & 63, jo = t >> 6;

#pragma unroll
    for (int it = 0; it < 8; it++) {
        const int jl = it * 4 + jo;
        const int j = jbase + jl;
        float g[4];
#pragma unroll
        for (int gt = 0; gt < 4; gt++) {
            size_t off = (size_t)(gt * 2048 + j) * 64 + b;
            float v = p0[off];
            if (p1)  v += p1[off];
            if (pre) v += pre[off];
            g[gt] = v + bias[gt * 2048 + j];
        }
        float si = 1.f / (1.f + __expf(-g[0]));
        float sf = 1.f / (1.f + __expf(-g[1]));
        float so = 1.f / (1.f + __expf(-g[3]));
        size_t ci = (size_t)j * 64 + b;
        float c2 = sf * c[ci] + si * tanhf(g[2]);
        float h2 = so * tanhf(c2);
        c[ci] = c2;
        bf hi = __float2bfloat16(h2);
        shh[jl][b] = hi;
        shl[jl][b] = __float2bfloat16(h2 - __bfloat162float(hi));
    }
    __syncthreads();
    const int bo = t >> 2, js = (t & 3) * 8;
    bf th[8], tl[8];
#pragma unroll
    for (int k = 0; k < 8; k++) { th[k] = shh[js + k][bo]; tl[k] = shl[js + k][bo]; }
    *(uint4*)(hh + (size_t)bo * 2048 + jbase + js) = *(uint4*)th;
    *(uint4*)(hl + (size_t)bo * 2048 + jbase + js) = *(uint4*)tl;
}

extern "C" void kernel_launch(void* const* d_in, const int* in_sizes, int n_in,
                              void* d_out, int out_size)
{
    const float* x        = (const float*)d_in[0];
    const float* fc_en1_w = (const float*)d_in[1];
    const float* fc_en1_b = (const float*)d_in[2];
    const float* fc_en2_w = (const float*)d_in[3];
    const float* fc_en2_b = (const float*)d_in[4];
    const float* en_wih   = (const float*)d_in[5];
    const float* en_whh   = (const float*)d_in[6];
    const float* en_b     = (const float*)d_in[7];
    const float* de_wih   = (const float*)d_in[8];
    const float* de_whh   = (const float*)d_in[9];
    const float* de_b     = (const float*)d_in[10];
    const float* fc_de1_w = (const float*)d_in[11];
    const float* fc_de1_b = (const float*)d_in[12];
    const float* fc_de2_w = (const float*)d_in[13];
    const float* fc_de2_b = (const float*)d_in[14];
    float* out = (float*)d_out;

    bf *ewih_h, *ewih_l, *ewhh_h, *ewhh_l, *dwih_h, *dwih_l, *dwhh_h, *dwhh_l;
    bf *fc1h, *fc1l, *fc2h, *fc2l, *fd1h, *fd1l, *fd2h, *fd2l;
    bf *xh, *xl, *f1ah, *f1al, *f2ah, *f2al, *d1ah, *d1al, *hah, *hal, *zero;
    float *parts, *pre, *c;
    cudaGetSymbolAddress((void**)&ewih_h, g_ewih_h); cudaGetSymbolAddress((void**)&ewih_l, g_ewih_l);
    cudaGetSymbolAddress((void**)&ewhh_h, g_ewhh_h); cudaGetSymbolAddress((void**)&ewhh_l, g_ewhh_l);
    cudaGetSymbolAddress((void**)&dwih_h, g_dwih_h); cudaGetSymbolAddress((void**)&dwih_l, g_dwih_l);
    cudaGetSymbolAddress((void**)&dwhh_h, g_dwhh_h); cudaGetSymbolAddress((void**)&dwhh_l, g_dwhh_l);
    cudaGetSymbolAddress((void**)&fc1h, g_fc1w_h);   cudaGetSymbolAddress((void**)&fc1l, g_fc1w_l);
    cudaGetSymbolAddress((void**)&fc2h, g_fc2w_h);   cudaGetSymbolAddress((void**)&fc2l, g_fc2w_l);
    cudaGetSymbolAddress((void**)&fd1h, g_fd1w_h);   cudaGetSymbolAddress((void**)&fd1l, g_fd1w_l);
    cudaGetSymbolAddress((void**)&fd2h, g_fd2w_h);   cudaGetSymbolAddress((void**)&fd2l, g_fd2w_l);
    cudaGetSymbolAddress((void**)&xh, g_xh);         cudaGetSymbolAddress((void**)&xl, g_xl);
    cudaGetSymbolAddress((void**)&f1ah, g_f1a_h);    cudaGetSymbolAddress((void**)&f1al, g_f1a_l);
    cudaGetSymbolAddress((void**)&f2ah, g_f2a_h);    cudaGetSymbolAddress((void**)&f2al, g_f2a_l);
    cudaGetSymbolAddress((void**)&d1ah, g_d1a_h);    cudaGetSymbolAddress((void**)&d1al, g_d1a_l);
    cudaGetSymbolAddress((void**)&hah, g_ha_h);      cudaGetSymbolAddress((void**)&hal, g_ha_l);
    cudaGetSymbolAddress((void**)&zero, g_zero);
    cudaGetSymbolAddress((void**)&parts, g_parts);   cudaGetSymbolAddress((void**)&pre, g_pre);
    cudaGetSymbolAddress((void**)&c, g_c);

    cudaFuncSetAttribute(gemm_ms, cudaFuncAttributeMaxDynamicSharedMemorySize, SMEM_SZ);

    const int HB = 131072;

    // ---- fused split prepass ----
    {
        SplitArgs a;
        const float* srcs[9] = {en_wih, en_whh, de_wih, de_whh, fc_en1_w,
                                fc_en2_w, fc_de1_w, fc_de2_w, x};
        bf* hs[9] = {ewih_h, ewhh_h, dwih_h, dwhh_h, fc1h, fc2h, fd1h, fd2h, xh};
        bf* ls[9] = {ewih_l, ewhh_l, dwih_l, dwhh_l, fc1l, fc2l, fd1l, fd2l, xl};
        long ns[9] = {3L*LWN, 3L*LWN, 3L*LWN, 3L*LWN, 4194304, 2097152,
                      2097152, 4194304, 4194304};
        long acc = 0;
        for (int i = 0; i < 9; i++) {
            a.s[i] = srcs[i]; a.h[i] = hs[i]; a.l[i] = ls[i];
            a.off4[i] = acc; acc += ns[i] / 4;
        }
        a.off4[9] = acc;
        split_all<<<2048, 256>>>(a);
    }

    cudaMemsetAsync(hah,  0, 3 * HB * sizeof(bf));
    cudaMemsetAsync(hal,  0, 3 * HB * sizeof(bf));
    cudaMemsetAsync(c,    0, 3 * HB * sizeof(float));
    cudaMemsetAsync(zero, 0, HB * sizeof(bf));

    // ---- encoder FCs batched over all 16 steps ----
    gemm_ms<<<dim3(16, 16), 256, SMEM_SZ>>>(fc1h, fc1l, xh, xl,
        nullptr, nullptr, nullptr, nullptr, fc_en1_b,
        nullptr, f1ah, f1al, 4096, 1024, 1, 0);
    gemm_ms<<<dim3(32, 16), 256, SMEM_SZ>>>(fc2h, fc2l, f1ah, f1al,
        nullptr, nullptr, nullptr, nullptr, fc_en2_b,
        nullptr, f2ah, f2al, 1024, 2048, 1, 0);

    // ---- encoder layer-0 Wih pre-gates, batched over all 16 steps ----
    gemm_ms<<<dim3(128, 16), 256, SMEM_SZ>>>(ewih_h, ewih_l, f2ah, f2al,
        nullptr, nullptr, nullptr, nullptr, nullptr,
        pre, nullptr, nullptr, 2048, 0, 0, 2);

    // ---- encoder LSTM ----
    for (int t = 0; t < 16; t++) {
        // layer 0: only Whh per step (Wih pre-computed)
        gemm_ms<<<dim3(128, 1), 256, SMEM_SZ>>>(
            ewhh_h, ewhh_l, hah, hal,
            nullptr, nullptr, nullptr, nullptr, nullptr,
            parts, nullptr, nullptr, 2048, 0, 0, 1);
        lstm_pw<<<64, 256>>>(parts, nullptr, pre + (size_t)t * 524288,
                             en_b, c, hah, hal);
        for (int l = 1; l < 3; l++) {
            gemm_ms<<<dim3(128, 2), 256, SMEM_SZ>>>(
                ewih_h + (size_t)l * LWN, ewih_l + (size_t)l * LWN,
                hah + (l - 1) * HB, hal + (l - 1) * HB,
                ewhh_h + (size_t)l * LWN, ewhh_l + (size_t)l * LWN,
                hah + l * HB, hal + l * HB, nullptr,
                parts, nullptr, nullptr, 2048, 0, 0, 1);
            lstm_pw<<<64, 256>>>(parts, parts + 524288, nullptr,
                                 en_b + l * 8192, c + l * HB,
                                 hah + l * HB, hal + l * HB);
        }
    }

    // ---- decoder init: h_d0 = h_e2, rest zero ----
    cudaMemcpyAsync(hah, hah + 2 * HB, HB * sizeof(bf), cudaMemcpyDeviceToDevice);
    cudaMemcpyAsync(hal, hal + 2 * HB, HB * sizeof(bf), cudaMemcpyDeviceToDevice);
    cudaMemsetAsync(hah + HB, 0, 2 * HB * sizeof(bf));
    cudaMemsetAsync(hal + HB, 0, 2 * HB * sizeof(bf));
    cudaMemsetAsync(c, 0, 3 * HB * sizeof(float));

    // ---- decoder ----
    for (int t = 0; t < 16; t++) {
        for (int l = 0; l < 3; l++) {
            const bf* ih = (l == 0) ? ((t == 0) ? zero : (hah + 2 * HB)) : (hah + (l - 1) * HB);
            const bf* il = (l == 0) ? ((t == 0) ? zero : (hal + 2 * HB)) : (hal + (l - 1) * HB);
            gemm_ms<<<dim3(128, 2), 256, SMEM_SZ>>>(
                dwih_h + (size_t)l * LWN, dwih_l + (size_t)l * LWN, ih, il,
                dwhh_h + (size_t)l * LWN, dwhh_l + (size_t)l * LWN,
                hah + l * HB, hal + l * HB, nullptr,
                parts, nullptr, nullptr, 2048, 0, 0, 1);
            lstm_pw<<<64, 256>>>(parts, parts + 524288, nullptr,
                                 de_b + l * 8192, c + l * HB,
                                 hah + l * HB, hal + l * HB);
        }
        gemm_ms<<<dim3(16, 1), 256, SMEM_SZ>>>(fd1h, fd1l, hah + 2 * HB, hal + 2 * HB,
            nullptr, nullptr, nullptr, nullptr, fc_de1_b,
            nullptr, d1ah, d1al, 2048, 1024, 1, 0);
        gemm_ms<<<dim3(64, 1), 256, SMEM_SZ>>>(fd2h, fd2l, d1ah, d1al,
            nullptr, nullptr, nullptr, nullptr, fc_de2_b,
            out + (size_t)t * 262144, nullptr, nullptr, 1024, 4096, 2, 0);
    }
}

// round 7
// speedup vs baseline: 4.3381x; 1.2786x over previous
#include <cuda_runtime.h>
#include <cuda_fp16.h>
#include <cstdint>
#include <cstddef>

typedef __half hf;

// ---------------- tile constants ----------------
#define TM    64
#define TN    64
#define ROWB  144                 // padded SMEM row (72 fp16) -> conflict-free ldmatrix
#define OFF_A  0
#define OFF_BH 9216
#define OFF_BL 18432
#define STAGE  27648
#define SMEM_SZ (4 * STAGE)       // 110592 B -> 2 CTAs/SM, 4-stage pipeline

// ---------------- asm helpers ----------------
__device__ __forceinline__ void cpa(uint32_t d, const void* s) {
    asm volatile("cp.async.cg.shared.global [%0], [%1], 16;" :: "r"(d), "l"(s));
}
__device__ __forceinline__ void cpcommit() {
    asm volatile("cp.async.commit_group;" ::: "memory");
}
template <int N> __device__ __forceinline__ void cpwait() {
    asm volatile("cp.async.wait_group %0;" :: "n"(N) : "memory");
}
#define LDSM4(R, addr) \
    asm volatile("ldmatrix.sync.aligned.m8n8.x4.shared.b16 {%0,%1,%2,%3}, [%4];" \
        : "=r"((R)[0]), "=r"((R)[1]), "=r"((R)[2]), "=r"((R)[3]) : "r"(addr))
#define MMA(D, A, b0, b1) \
    asm volatile("mma.sync.aligned.m16n8k16.row.col.f32.f16.f16.f32 " \
        "{%0,%1,%2,%3}, {%4,%5,%6,%7}, {%8,%9}, {%0,%1,%2,%3};" \
        : "+f"((D)[0]), "+f"((D)[1]), "+f"((D)[2]), "+f"((D)[3]) \
        : "r"((A)[0]), "r"((A)[1]), "r"((A)[2]), "r"((A)[3]), "r"(b0), "r"(b1))

// ---------------- scratch ----------------
#define LWN 16777216               // 8192*2048
__device__ hf g_ewih[3*LWN], g_ewhh[3*LWN];
__device__ hf g_dwih[3*LWN], g_dwhh[3*LWN];
__device__ hf g_fc1w[4194304], g_fc2w[2097152];
__device__ hf g_fd1w[2097152], g_fd2w[4194304];
__device__ hf g_xh[4194304],   g_xl[4194304];         // [1024,4096]
__device__ hf g_f1a_h[1048576], g_f1a_l[1048576];     // [1024,1024]
__device__ hf g_f2a_h[2097152], g_f2a_l[2097152];     // [1024,2048]
__device__ hf g_d1a_h[65536],  g_d1a_l[65536];        // [64,1024]
__device__ hf g_ha_h[393216],  g_ha_l[393216];        // 3 x [64,2048] batch-major
__device__ hf g_zero[131072];
__device__ float g_parts[2 * 524288];                 // 2 x [8192,64] f-major
__device__ float g_pre[16 * 524288];                  // enc-l0 pre-gates per step
__device__ float g_c[393216];                         // 3 x [2048,64] f-major

// ===========================================================================
// Fused split prepass: fp32 -> fp16 hi (+lo if wanted), 9 tensors, one launch
// ===========================================================================
struct SplitArgs {
    const float* s[9];
    hf* h[9];
    hf* l[9];        // null -> hi only
    long off4[10];
};

__global__ void __launch_bounds__(256) split_all(SplitArgs a)
{
    const long total = a.off4[9];
    for (long v = (long)blockIdx.x * 256 + threadIdx.x; v < total;
         v += (long)gridDim.x * 256) {
        int seg = 0;
#pragma unroll
        for (int i = 0; i < 8; i++) seg += (v >= a.off4[i + 1]) ? 1 : 0;
        long e = (v - a.off4[seg]) * 4;
        float4 x = *(const float4*)(a.s[seg] + e);
        hf h0 = __float2half_rn(x.x), h1 = __float2half_rn(x.y);
        hf h2 = __float2half_rn(x.z), h3 = __float2half_rn(x.w);
        uint2 ph;
        ph.x = (uint32_t)*(uint16_t*)&h0 | ((uint32_t)*(uint16_t*)&h1 << 16);
        ph.y = (uint32_t)*(uint16_t*)&h2 | ((uint32_t)*(uint16_t*)&h3 << 16);
        *(uint2*)(a.h[seg] + e) = ph;
        if (a.l[seg]) {
            hf l0 = __float2half_rn(x.x - __half2float(h0));
            hf l1 = __float2half_rn(x.y - __half2float(h1));
            hf l2 = __float2half_rn(x.z - __half2float(h2));
            hf l3 = __float2half_rn(x.w - __half2float(h3));
            uint2 pl;
            pl.x = (uint32_t)*(uint16_t*)&l0 | ((uint32_t)*(uint16_t*)&l1 << 16);
            pl.y = (uint32_t)*(uint16_t*)&l2 | ((uint32_t)*(uint16_t*)&l3 << 16);
            *(uint2*)(a.l[seg] + e) = pl;
        }
    }
}

// ===========================================================================
// fp16 2-term mma.sync GEMM: D[f,b] = sum_k W[f,k] * (acth+actl)[b,k]
// W single fp16; activations hi/lo fp16. 4-stage cp.async pipeline.
// dual=1: grid.y = slot (0/1 operand set), f-major partial to outf+y*524288
// dual=2: grid.y = token tile, f-major store to outf+y*524288 (slot0 ops)
// dual=0: grid.y = token tile; mode 0 fp32+bias, 1 relu+split, 2 sigmoid
// ===========================================================================
__global__ void __launch_bounds__(256, 2)
gemm_ms(const hf* __restrict__ A0, const hf* __restrict__ Bh0, const hf* __restrict__ Bl0,
        const hf* __restrict__ A1, const hf* __restrict__ Bh1, const hf* __restrict__ Bl1,
        const float* __restrict__ bias,
        float* __restrict__ outf, hf* __restrict__ outh, hf* __restrict__ outl,
        int K, int ldc, int mode, int dual)
{
    extern __shared__ char smem[];
    const uint32_t sb = (uint32_t)__cvta_generic_to_shared(smem);
    const int t = threadIdx.x;
    const int fbase = blockIdx.x * TM;

    const hf *A, *Bh, *Bl;
    int nbase = 0;
    if (dual == 1 && blockIdx.y == 1) { A = A1; Bh = Bh1; Bl = Bl1; }
    else {
        A = A0; Bh = Bh0; Bl = Bl0;
        if (dual != 1) nbase = blockIdx.y * TN;
    }
    const hf* aP = A  + (size_t)fbase * K;
    const hf* bH = Bh + (size_t)nbase * K;
    const hf* bL = Bl + (size_t)nbase * K;
    const int NC = K >> 6;

    const int r0 = t >> 3, seg = t & 7;
    auto issue = [&](int chunk) {
        const uint32_t st = sb + (chunk & 3) * STAGE;
        const int koff = (chunk << 6) + seg * 8;
#pragma unroll
        for (int i = 0; i < 2; i++) {
            int row = r0 + i * 32;
            uint32_t d = st + row * ROWB + seg * 16;
            cpa(d + OFF_A,  aP + (size_t)row * K + koff);
            cpa(d + OFF_BH, bH + (size_t)row * K + koff);
            cpa(d + OFF_BL, bL + (size_t)row * K + koff);
        }
    };

    issue(0); cpcommit();
    issue(1); cpcommit();
    issue(2); cpcommit();

    const int w = t >> 5, lane = t & 31;
    const int moff = (w & 1) * 32;
    const int noff = (w >> 1) * 16;
    const int arow = lane & 15, ahalf = lane >> 4;
    const int bj = lane >> 3;
    const int brow = ((bj >> 1) * 8) + (lane & 7), bkh = bj & 1;

    float d[2][2][4];
#pragma unroll
    for (int mi = 0; mi < 2; mi++)
#pragma unroll
        for (int nj = 0; nj < 2; nj++)
#pragma unroll
            for (int q = 0; q < 4; q++) d[mi][nj][q] = 0.f;

    for (int s = 0; s < NC; s++) {
        cpwait<2>();
        __syncthreads();
        const uint32_t st = sb + (s & 3) * STAGE;
#pragma unroll
        for (int k16 = 0; k16 < 4; k16++) {
            const int kb = k16 * 32;
            uint32_t ah[2][4], bh[4], bl[4];
#pragma unroll
            for (int mi = 0; mi < 2; mi++) {
                uint32_t ra = (uint32_t)((moff + mi * 16 + arow) * ROWB + kb + ahalf * 16);
                LDSM4(ah[mi], st + OFF_A + ra);
            }
            {
                uint32_t rb = (uint32_t)((noff + brow) * ROWB + kb + bkh * 16);
                LDSM4(bh, st + OFF_BH + rb);
                LDSM4(bl, st + OFF_BL + rb);
            }
#pragma unroll
            for (int mi = 0; mi < 2; mi++)
#pragma unroll
                for (int nj = 0; nj < 2; nj++) {
                    const int p = nj * 2;
                    MMA(d[mi][nj], ah[mi], bh[p], bh[p + 1]);
                    MMA(d[mi][nj], ah[mi], bl[p], bl[p + 1]);
                }
        }
        if (s + 3 < NC) issue(s + 3);
        cpcommit();
    }

    const int rr = lane >> 2, cc = (lane & 3) * 2;

    if (dual) {
        float* po = outf + (size_t)blockIdx.y * 524288;
#pragma unroll
        for (int mi = 0; mi < 2; mi++)
#pragma unroll
            for (int nj = 0; nj < 2; nj++) {
                int m = moff + mi * 16 + rr;
                int n = noff + nj * 8 + cc;
                *(float2*)(po + (size_t)(fbase + m) * 64 + n) =
                    make_float2(d[mi][nj][0], d[mi][nj][1]);
                *(float2*)(po + (size_t)(fbase + m + 8) * 64 + n) =
                    make_float2(d[mi][nj][2], d[mi][nj][3]);
            }
        return;
    }

    // batch-major epilogue with fused activation
    __syncthreads();
    float* cs = (float*)smem;                   // [64][68]
#pragma unroll
    for (int mi = 0; mi < 2; mi++)
#pragma unroll
        for (int nj = 0; nj < 2; nj++) {
            int m = moff + mi * 16 + rr;
            int n = noff + nj * 8 + cc;
            cs[n * 68 + m]           = d[mi][nj][0];
            cs[(n + 1) * 68 + m]     = d[mi][nj][1];
            cs[n * 68 + m + 8]       = d[mi][nj][2];
            cs[(n + 1) * 68 + m + 8] = d[mi][nj][3];
        }
    __syncthreads();

    const int b = t >> 2, j0 = (t & 3) * 16;
    const float* bp = bias + fbase + j0;
    if (mode == 0) {
        float* dst = outf + (size_t)(nbase + b) * ldc + fbase + j0;
#pragma unroll
        for (int j = 0; j < 16; j++) dst[j] = cs[b * 68 + j0 + j] + bp[j];
    } else if (mode == 1) {
        hf* dh = outh + (size_t)(nbase + b) * ldc + fbase + j0;
        hf* dl = outl + (size_t)(nbase + b) * ldc + fbase + j0;
#pragma unroll
        for (int j = 0; j < 16; j++) {
            float v = fmaxf(cs[b * 68 + j0 + j] + bp[j], 0.f);
            hf hi = __float2half_rn(v);
            dh[j] = hi;
            dl[j] = __float2half_rn(v - __half2float(hi));
        }
    } else {
        float* dst = outf + (size_t)(nbase + b) * ldc + fbase + j0;
#pragma unroll
        for (int j = 0; j < 16; j++) {
            float v = cs[b * 68 + j0 + j] + bp[j];
            dst[j] = 1.f / (1.f + __expf(-v));
        }
    }
}

// ===========================================================================
// LSTM pointwise: g = p0 + (p1?) + (pre?) + bias  (f-major [8192,64]);
// update f-major c; write batch-major h (hi/lo fp16) via smem transpose.
// ===========================================================================
__global__ void __launch_bounds__(256) lstm_pw(
    const float* __restrict__ p0, const float* __restrict__ p1,
    const float* __restrict__ pre, const float* __restrict__ bias,
    float* __restrict__ c, hf* __restrict__ hh, hf* __restrict__ hl)
{
    __shared__ hf shh[32][65], shl[32][65];
    const int t = threadIdx.x;
    const int jbase = blockIdx.x * 32;
    const int b = t & 63, jo = t >> 6;

#pragma unroll
    for (int it = 0; it < 8; it++) {
        const int jl = it * 4 + jo;
        const int j = jbase + jl;
        float g[4];
#pragma unroll
        for (int gt = 0; gt < 4; gt++) {
            size_t off = (size_t)(gt * 2048 + j) * 64 + b;
            float v = p0[off];
            if (p1)  v += p1[off];
            if (pre) v += pre[off];
            g[gt] = v + bias[gt * 2048 + j];
        }
        float si = 1.f / (1.f + __expf(-g[0]));
        float sf = 1.f / (1.f + __expf(-g[1]));
        float so = 1.f / (1.f + __expf(-g[3]));
        size_t ci = (size_t)j * 64 + b;
        float c2 = sf * c[ci] + si * tanhf(g[2]);
        float h2 = so * tanhf(c2);
        c[ci] = c2;
        hf hi = __float2half_rn(h2);
        shh[jl][b] = hi;
        shl[jl][b] = __float2half_rn(h2 - __half2float(hi));
    }
    __syncthreads();
    const int bo = t >> 2, js = (t & 3) * 8;
    hf th[8], tl[8];
#pragma unroll
    for (int k = 0; k < 8; k++) { th[k] = shh[js + k][bo]; tl[k] = shl[js + k][bo]; }
    *(uint4*)(hh + (size_t)bo * 2048 + jbase + js) = *(uint4*)th;
    *(uint4*)(hl + (size_t)bo * 2048 + jbase + js) = *(uint4*)tl;
}

extern "C" void kernel_launch(void* const* d_in, const int* in_sizes, int n_in,
                              void* d_out, int out_size)
{
    const float* x        = (const float*)d_in[0];
    const float* fc_en1_w = (const float*)d_in[1];
    const float* fc_en1_b = (const float*)d_in[2];
    const float* fc_en2_w = (const float*)d_in[3];
    const float* fc_en2_b = (const float*)d_in[4];
    const float* en_wih   = (const float*)d_in[5];
    const float* en_whh   = (const float*)d_in[6];
    const float* en_b     = (const float*)d_in[7];
    const float* de_wih   = (const float*)d_in[8];
    const float* de_whh   = (const float*)d_in[9];
    const float* de_b     = (const float*)d_in[10];
    const float* fc_de1_w = (const float*)d_in[11];
    const float* fc_de1_b = (const float*)d_in[12];
    const float* fc_de2_w = (const float*)d_in[13];
    const float* fc_de2_b = (const float*)d_in[14];
    float* out = (float*)d_out;

    hf *ewih, *ewhh, *dwih, *dwhh, *fc1w, *fc2w, *fd1w, *fd2w;
    hf *xh, *xl, *f1ah, *f1al, *f2ah, *f2al, *d1ah, *d1al, *hah, *hal, *zero;
    float *parts, *pre, *c;
    cudaGetSymbolAddress((void**)&ewih, g_ewih);   cudaGetSymbolAddress((void**)&ewhh, g_ewhh);
    cudaGetSymbolAddress((void**)&dwih, g_dwih);   cudaGetSymbolAddress((void**)&dwhh, g_dwhh);
    cudaGetSymbolAddress((void**)&fc1w, g_fc1w);   cudaGetSymbolAddress((void**)&fc2w, g_fc2w);
    cudaGetSymbolAddress((void**)&fd1w, g_fd1w);   cudaGetSymbolAddress((void**)&fd2w, g_fd2w);
    cudaGetSymbolAddress((void**)&xh, g_xh);       cudaGetSymbolAddress((void**)&xl, g_xl);
    cudaGetSymbolAddress((void**)&f1ah, g_f1a_h);  cudaGetSymbolAddress((void**)&f1al, g_f1a_l);
    cudaGetSymbolAddress((void**)&f2ah, g_f2a_h);  cudaGetSymbolAddress((void**)&f2al, g_f2a_l);
    cudaGetSymbolAddress((void**)&d1ah, g_d1a_h);  cudaGetSymbolAddress((void**)&d1al, g_d1a_l);
    cudaGetSymbolAddress((void**)&hah, g_ha_h);    cudaGetSymbolAddress((void**)&hal, g_ha_l);
    cudaGetSymbolAddress((void**)&zero, g_zero);
    cudaGetSymbolAddress((void**)&parts, g_parts); cudaGetSymbolAddress((void**)&pre, g_pre);
    cudaGetSymbolAddress((void**)&c, g_c);

    cudaFuncSetAttribute(gemm_ms, cudaFuncAttributeMaxDynamicSharedMemorySize, SMEM_SZ);

    const int HB = 131072;

    // ---- fused split prepass ----
    {
        SplitArgs a;
        const float* srcs[9] = {en_wih, en_whh, de_wih, de_whh, fc_en1_w,
                                fc_en2_w, fc_de1_w, fc_de2_w, x};
        hf* hs[9] = {ewih, ewhh, dwih, dwhh, fc1w, fc2w, fd1w, fd2w, xh};
        hf* ls[9] = {nullptr, nullptr, nullptr, nullptr, nullptr,
                     nullptr, nullptr, nullptr, xl};
        long ns[9] = {3L*LWN, 3L*LWN, 3L*LWN, 3L*LWN, 4194304, 2097152,
                      2097152, 4194304, 4194304};
        long acc = 0;
        for (int i = 0; i < 9; i++) {
            a.s[i] = srcs[i]; a.h[i] = hs[i]; a.l[i] = ls[i];
            a.off4[i] = acc; acc += ns[i] / 4;
        }
        a.off4[9] = acc;
        split_all<<<2048, 256>>>(a);
    }

    cudaMemsetAsync(hah,  0, 3 * HB * sizeof(hf));
    cudaMemsetAsync(hal,  0, 3 * HB * sizeof(hf));
    cudaMemsetAsync(c,    0, 3 * HB * sizeof(float));
    cudaMemsetAsync(zero, 0, HB * sizeof(hf));

    // ---- encoder FCs batched over all 16 steps ----
    gemm_ms<<<dim3(16, 16), 256, SMEM_SZ>>>(fc1w, xh, xl,
        nullptr, nullptr, nullptr, fc_en1_b,
        nullptr, f1ah, f1al, 4096, 1024, 1, 0);
    gemm_ms<<<dim3(32, 16), 256, SMEM_SZ>>>(fc2w, f1ah, f1al,
        nullptr, nullptr, nullptr, fc_en2_b,
        nullptr, f2ah, f2al, 1024, 2048, 1, 0);

    // ---- encoder layer-0 Wih pre-gates, batched over all 16 steps ----
    gemm_ms<<<dim3(128, 16), 256, SMEM_SZ>>>(ewih, f2ah, f2al,
        nullptr, nullptr, nullptr, nullptr,
        pre, nullptr, nullptr, 2048, 0, 0, 2);

    // ---- encoder LSTM ----
    for (int t = 0; t < 16; t++) {
        gemm_ms<<<dim3(128, 1), 256, SMEM_SZ>>>(
            ewhh, hah, hal, nullptr, nullptr, nullptr, nullptr,
            parts, nullptr, nullptr, 2048, 0, 0, 1);
        lstm_pw<<<64, 256>>>(parts, nullptr, pre + (size_t)t * 524288,
                             en_b, c, hah, hal);
        for (int l = 1; l < 3; l++) {
            gemm_ms<<<dim3(128, 2), 256, SMEM_SZ>>>(
                ewih + (size_t)l * LWN, hah + (l - 1) * HB, hal + (l - 1) * HB,
                ewhh + (size_t)l * LWN, hah + l * HB, hal + l * HB, nullptr,
                parts, nullptr, nullptr, 2048, 0, 0, 1);
            lstm_pw<<<64, 256>>>(parts, parts + 524288, nullptr,
                                 en_b + l * 8192, c + l * HB,
                                 hah + l * HB, hal + l * HB);
        }
    }

    // ---- decoder init: h_d0 = h_e2, rest zero ----
    cudaMemcpyAsync(hah, hah + 2 * HB, HB * sizeof(hf), cudaMemcpyDeviceToDevice);
    cudaMemcpyAsync(hal, hal + 2 * HB, HB * sizeof(hf), cudaMemcpyDeviceToDevice);
    cudaMemsetAsync(hah + HB, 0, 2 * HB * sizeof(hf));
    cudaMemsetAsync(hal + HB, 0, 2 * HB * sizeof(hf));
    cudaMemsetAsync(c, 0, 3 * HB * sizeof(float));

    // ---- decoder ----
    for (int t = 0; t < 16; t++) {
        for (int l = 0; l < 3; l++) {
            const hf* ih = (l == 0) ? ((t == 0) ? zero : (hah + 2 * HB)) : (hah + (l - 1) * HB);
            const hf* il = (l == 0) ? ((t == 0) ? zero : (hal + 2 * HB)) : (hal + (l - 1) * HB);
            gemm_ms<<<dim3(128, 2), 256, SMEM_SZ>>>(
                dwih + (size_t)l * LWN, ih, il,
                dwhh + (size_t)l * LWN, hah + l * HB, hal + l * HB, nullptr,
                parts, nullptr, nullptr, 2048, 0, 0, 1);
            lstm_pw<<<64, 256>>>(parts, parts + 524288, nullptr,
                                 de_b + l * 8192, c + l * HB,
                                 hah + l * HB, hal + l * HB);
        }
        gemm_ms<<<dim3(16, 1), 256, SMEM_SZ>>>(fd1w, hah + 2 * HB, hal + 2 * HB,
            nullptr, nullptr, nullptr, fc_de1_b,
            nullptr, d1ah, d1al, 2048, 1024, 1, 0);
        gemm_ms<<<dim3(64, 1), 256, SMEM_SZ>>>(fd2w, d1ah, d1al,
            nullptr, nullptr, nullptr, fc_de2_b,
            out + (size_t)t * 262144, nullptr, nullptr, 1024, 4096, 2, 0);
    }
}

// round 8
// speedup vs baseline: 4.5399x; 1.0465x over previous
#include <cuda_runtime.h>
#include <cuda_fp16.h>
#include <cstdint>
#include <cstddef>

typedef __half hf;

// ---------------- tile constants ----------------
#define TM    64
#define TN    64
#define ROWB  144                 // padded SMEM row (72 fp16) -> conflict-free ldmatrix
#define OFF_A  0
#define OFF_BH 9216
#define OFF_BL 18432
#define STAGE  27648
#define SMEM_SZ (4 * STAGE)       // 110592 B

// ---------------- asm helpers ----------------
__device__ __forceinline__ void cpa(uint32_t d, const void* s) {
    asm volatile("cp.async.cg.shared.global [%0], [%1], 16;" :: "r"(d), "l"(s));
}
__device__ __forceinline__ void cpcommit() {
    asm volatile("cp.async.commit_group;" ::: "memory");
}
template <int N> __device__ __forceinline__ void cpwait() {
    asm volatile("cp.async.wait_group %0;" :: "n"(N) : "memory");
}
#define LDSM4(R, addr) \
    asm volatile("ldmatrix.sync.aligned.m8n8.x4.shared.b16 {%0,%1,%2,%3}, [%4];" \
        : "=r"((R)[0]), "=r"((R)[1]), "=r"((R)[2]), "=r"((R)[3]) : "r"(addr))
#define MMA(D, A, b0, b1) \
    asm volatile("mma.sync.aligned.m16n8k16.row.col.f32.f16.f16.f32 " \
        "{%0,%1,%2,%3}, {%4,%5,%6,%7}, {%8,%9}, {%0,%1,%2,%3};" \
        : "+f"((D)[0]), "+f"((D)[1]), "+f"((D)[2]), "+f"((D)[3]) \
        : "r"((A)[0]), "r"((A)[1]), "r"((A)[2]), "r"((A)[3]), "r"(b0), "r"(b1))

// ---------------- scratch ----------------
#define LWF 16777216               // 8192*2048 (one fp32 LSTM matrix, elems)
#define WCATN 33554432             // 8192*4096 per cat matrix
__device__ hf g_wcat[5 * WCATN];                     // enc l1,l2; dec l0,l1,l2
__device__ hf g_ewhh0[LWF];                          // enc l0 Whh, interleaved
__device__ hf g_ewih0[LWF];                          // enc l0 Wih, FLAT (pre-gates)
__device__ hf g_fc1w[4194304], g_fc2w[2097152];
__device__ hf g_fd1w[2097152], g_fd2w[4194304];
__device__ hf g_xh[4194304],   g_xl[4194304];        // [1024,4096]
__device__ hf g_f1a_h[1048576], g_f1a_l[1048576];
__device__ hf g_f2a_h[2097152], g_f2a_l[2097152];    // [1024,2048]
__device__ hf g_d1a_h[65536],  g_d1a_l[65536];
__device__ hf g_hH[6 * 131072], g_hL[6 * 131072];    // [layer][parity][64,2048]
__device__ float g_pre[16 * 524288];                 // enc-l0 pre-gates, f-major
__device__ float g_c[3 * 131072];                    // [layer][64,2048] batch-major

// ===========================================================================
// split prepass (FC weights hi, x hi/lo, enc-l0 Wih flat hi)
// ===========================================================================
struct SplitArgs {
    const float* s[9];
    hf* h[9];
    hf* l[9];
    long off4[10];
};

__global__ void __launch_bounds__(256) split_all(SplitArgs a)
{
    const long total = a.off4[9];
    for (long v = (long)blockIdx.x * 256 + threadIdx.x; v < total;
         v += (long)gridDim.x * 256) {
        int seg = 0;
#pragma unroll
        for (int i = 0; i < 8; i++) seg += (v >= a.off4[i + 1]) ? 1 : 0;
        long e = (v - a.off4[seg]) * 4;
        float4 x = *(const float4*)(a.s[seg] + e);
        hf h0 = __float2half_rn(x.x), h1 = __float2half_rn(x.y);
        hf h2 = __float2half_rn(x.z), h3 = __float2half_rn(x.w);
        uint2 ph;
        ph.x = (uint32_t)*(uint16_t*)&h0 | ((uint32_t)*(uint16_t*)&h1 << 16);
        ph.y = (uint32_t)*(uint16_t*)&h2 | ((uint32_t)*(uint16_t*)&h3 << 16);
        *(uint2*)(a.h[seg] + e) = ph;
        if (a.l[seg]) {
            hf l0 = __float2half_rn(x.x - __half2float(h0));
            hf l1 = __float2half_rn(x.y - __half2float(h1));
            hf l2 = __float2half_rn(x.z - __half2float(h2));
            hf l3 = __float2half_rn(x.w - __half2float(h3));
            uint2 pl;
            pl.x = (uint32_t)*(uint16_t*)&l0 | ((uint32_t)*(uint16_t*)&l1 << 16);
            pl.y = (uint32_t)*(uint16_t*)&l2 | ((uint32_t)*(uint16_t*)&l3 << 16);
            *(uint2*)(a.l[seg] + e) = pl;
        }
    }
}

// ===========================================================================
// LSTM weight pack: gate-interleave rows (r = jblk*64 + gate*16 + jin) and
// concat [Wih | Whh] along K. hasx=0 -> Whh only (K=2048).
// ===========================================================================
__global__ void __launch_bounds__(256) lstm_pack(
    const float* __restrict__ wih, const float* __restrict__ whh,
    hf* __restrict__ dst, int hasx)
{
    const int K = hasx ? 4096 : 2048;
    const long total = (long)8192 * K / 4;
    for (long v = (long)blockIdx.x * 256 + threadIdx.x; v < total;
         v += (long)gridDim.x * 256) {
        int r = (int)(v / (K >> 2));
        int c = (int)(v % (K >> 2)) * 4;
        int gate = (r >> 4) & 3, jblk = r >> 6, jin = r & 15;
        int orig = gate * 2048 + jblk * 16 + jin;
        const float* src = (c < 2048 || !hasx)
            ? (hasx ? wih : whh) + (size_t)orig * 2048 + (c & 2047)
            : whh + (size_t)orig * 2048 + (c - 2048);
        float4 x = *(const float4*)src;
        hf h0 = __float2half_rn(x.x), h1 = __float2half_rn(x.y);
        hf h2 = __float2half_rn(x.z), h3 = __float2half_rn(x.w);
        uint2 ph;
        ph.x = (uint32_t)*(uint16_t*)&h0 | ((uint32_t)*(uint16_t*)&h1 << 16);
        ph.y = (uint32_t)*(uint16_t*)&h2 | ((uint32_t)*(uint16_t*)&h3 << 16);
        *(uint2*)(dst + (size_t)r * K + c) = ph;
    }
}

// ===========================================================================
// FC GEMM (fp16 2-term): D[f,b] = sum_k W[f,k]*(acth+actl)[b,k]
// dual=2: grid.y = token tile, f-major store to outf + y*524288
// dual=0: grid.y = token tile; mode 0 fp32+bias, 1 relu+split, 2 sigmoid
// ===========================================================================
__global__ void __launch_bounds__(256, 2)
gemm_ms(const hf* __restrict__ A0, const hf* __restrict__ Bh0, const hf* __restrict__ Bl0,
        const float* __restrict__ bias,
        float* __restrict__ outf, hf* __restrict__ outh, hf* __restrict__ outl,
        int K, int ldc, int mode, int dual)
{
    extern __shared__ char smem[];
    const uint32_t sb = (uint32_t)__cvta_generic_to_shared(smem);
    const int t = threadIdx.x;
    const int fbase = blockIdx.x * TM;
    const int nbase = blockIdx.y * TN;

    const hf* aP = A0  + (size_t)fbase * K;
    const hf* bH = Bh0 + (size_t)nbase * K;
    const hf* bL = Bl0 + (size_t)nbase * K;
    const int NC = K >> 6;

    const int r0 = t >> 3, seg = t & 7;
    auto issue = [&](int chunk) {
        const uint32_t st = sb + (chunk & 3) * STAGE;
        const int koff = (chunk << 6) + seg * 8;
#pragma unroll
        for (int i = 0; i < 2; i++) {
            int row = r0 + i * 32;
            uint32_t d = st + row * ROWB + seg * 16;
            cpa(d + OFF_A,  aP + (size_t)row * K + koff);
            cpa(d + OFF_BH, bH + (size_t)row * K + koff);
            cpa(d + OFF_BL, bL + (size_t)row * K + koff);
        }
    };

    issue(0); cpcommit();
    issue(1); cpcommit();
    issue(2); cpcommit();

    const int w = t >> 5, lane = t & 31;
    const int moff = (w & 1) * 32;
    const int noff = (w >> 1) * 16;
    const int arow = lane & 15, ahalf = lane >> 4;
    const int bj = lane >> 3;
    const int brow = ((bj >> 1) * 8) + (lane & 7), bkh = bj & 1;

    float d[2][2][4];
#pragma unroll
    for (int mi = 0; mi < 2; mi++)
#pragma unroll
        for (int nj = 0; nj < 2; nj++)
#pragma unroll
            for (int q = 0; q < 4; q++) d[mi][nj][q] = 0.f;

    for (int s = 0; s < NC; s++) {
        cpwait<2>();
        __syncthreads();
        const uint32_t st = sb + (s & 3) * STAGE;
#pragma unroll
        for (int k16 = 0; k16 < 4; k16++) {
            const int kb = k16 * 32;
            uint32_t ah[2][4], bh[4], bl[4];
#pragma unroll
            for (int mi = 0; mi < 2; mi++) {
                uint32_t ra = (uint32_t)((moff + mi * 16 + arow) * ROWB + kb + ahalf * 16);
                LDSM4(ah[mi], st + OFF_A + ra);
            }
            {
                uint32_t rb = (uint32_t)((noff + brow) * ROWB + kb + bkh * 16);
                LDSM4(bh, st + OFF_BH + rb);
                LDSM4(bl, st + OFF_BL + rb);
            }
#pragma unroll
            for (int mi = 0; mi < 2; mi++)
#pragma unroll
                for (int nj = 0; nj < 2; nj++) {
                    const int p = nj * 2;
                    MMA(d[mi][nj], ah[mi], bh[p], bh[p + 1]);
                    MMA(d[mi][nj], ah[mi], bl[p], bl[p + 1]);
                }
        }
        if (s + 3 < NC) issue(s + 3);
        cpcommit();
    }

    const int rr = lane >> 2, cc = (lane & 3) * 2;

    if (dual == 2) {
        float* po = outf + (size_t)blockIdx.y * 524288;
#pragma unroll
        for (int mi = 0; mi < 2; mi++)
#pragma unroll
            for (int nj = 0; nj < 2; nj++) {
                int m = moff + mi * 16 + rr;
                int n = noff + nj * 8 + cc;
                *(float2*)(po + (size_t)(fbase + m) * 64 + n) =
                    make_float2(d[mi][nj][0], d[mi][nj][1]);
                *(float2*)(po + (size_t)(fbase + m + 8) * 64 + n) =
                    make_float2(d[mi][nj][2], d[mi][nj][3]);
            }
        return;
    }

    __syncthreads();
    float* cs = (float*)smem;                   // [64][68] batch-major
#pragma unroll
    for (int mi = 0; mi < 2; mi++)
#pragma unroll
        for (int nj = 0; nj < 2; nj++) {
            int m = moff + mi * 16 + rr;
            int n = noff + nj * 8 + cc;
            cs[n * 68 + m]           = d[mi][nj][0];
            cs[(n + 1) * 68 + m]     = d[mi][nj][1];
            cs[n * 68 + m + 8]       = d[mi][nj][2];
            cs[(n + 1) * 68 + m + 8] = d[mi][nj][3];
        }
    __syncthreads();

    const int b = t >> 2, j0 = (t & 3) * 16;
    const float* bp = bias + fbase + j0;
    if (mode == 0) {
        float* dst = outf + (size_t)(nbase + b) * ldc + fbase + j0;
#pragma unroll
        for (int j = 0; j < 16; j++) dst[j] = cs[b * 68 + j0 + j] + bp[j];
    } else if (mode == 1) {
        hf* dh = outh + (size_t)(nbase + b) * ldc + fbase + j0;
        hf* dl = outl + (size_t)(nbase + b) * ldc + fbase + j0;
#pragma unroll
        for (int j = 0; j < 16; j++) {
            float v = fmaxf(cs[b * 68 + j0 + j] + bp[j], 0.f);
            hf hi = __float2half_rn(v);
            dh[j] = hi;
            dl[j] = __float2half_rn(v - __half2float(hi));
        }
    } else {
        float* dst = outf + (size_t)(nbase + b) * ldc + fbase + j0;
#pragma unroll
        for (int j = 0; j < 16; j++) {
            float v = cs[b * 68 + j0 + j] + bp[j];
            dst[j] = 1.f / (1.f + __expf(-v));
        }
    }
}

// ===========================================================================
// FUSED LSTM layer-step: gates GEMM (gate-interleaved W, K = Kx + 2048 over
// [x | h]) + pointwise epilogue (bias, sigmoids/tanh, c update, h hi/lo).
// grid = 128 CTAs; each CTA owns 16 hidden units x 64 batch.
// ===========================================================================
__global__ void __launch_bounds__(256, 2)
lstm_fused(const hf* __restrict__ W,
           const hf* __restrict__ BxH, const hf* __restrict__ BxL,
           const hf* __restrict__ BhH, const hf* __restrict__ BhL,
           const float* __restrict__ pre, const float* __restrict__ bias,
           float* __restrict__ c, hf* __restrict__ hh, hf* __restrict__ hl,
           int Kx)
{
    extern __shared__ char smem[];
    const uint32_t sb = (uint32_t)__cvta_generic_to_shared(smem);
    const int t = threadIdx.x;
    const int K = Kx + 2048;
    const int NC = K >> 6;
    const hf* aP = W + (size_t)(blockIdx.x * TM) * K;

    const int r0 = t >> 3, seg = t & 7;
    auto issue = [&](int chunk) {
        const uint32_t st = sb + (chunk & 3) * STAGE;
        const int kg = chunk << 6;
        const hf *bh, *bl; int ks;
        if (kg < Kx) { bh = BxH; bl = BxL; ks = kg; }
        else         { bh = BhH; bl = BhL; ks = kg - Kx; }
#pragma unroll
        for (int i = 0; i < 2; i++) {
            int row = r0 + i * 32;
            uint32_t d = st + row * ROWB + seg * 16;
            cpa(d + OFF_A,  aP + (size_t)row * K + kg + seg * 8);
            cpa(d + OFF_BH, bh + (size_t)row * 2048 + ks + seg * 8);
            cpa(d + OFF_BL, bl + (size_t)row * 2048 + ks + seg * 8);
        }
    };

    issue(0); cpcommit();
    issue(1); cpcommit();
    issue(2); cpcommit();

    const int w = t >> 5, lane = t & 31;
    const int moff = (w & 1) * 32;
    const int noff = (w >> 1) * 16;
    const int arow = lane & 15, ahalf = lane >> 4;
    const int bj = lane >> 3;
    const int brow = ((bj >> 1) * 8) + (lane & 7), bkh = bj & 1;

    float d[2][2][4];
#pragma unroll
    for (int mi = 0; mi < 2; mi++)
#pragma unroll
        for (int nj = 0; nj < 2; nj++)
#pragma unroll
            for (int q = 0; q < 4; q++) d[mi][nj][q] = 0.f;

    for (int s = 0; s < NC; s++) {
        cpwait<2>();
        __syncthreads();
        const uint32_t st = sb + (s & 3) * STAGE;
#pragma unroll
        for (int k16 = 0; k16 < 4; k16++) {
            const int kb = k16 * 32;
            uint32_t ah[2][4], bh[4], bl[4];
#pragma unroll
            for (int mi = 0; mi < 2; mi++) {
                uint32_t ra = (uint32_t)((moff + mi * 16 + arow) * ROWB + kb + ahalf * 16);
                LDSM4(ah[mi], st + OFF_A + ra);
            }
            {
                uint32_t rb = (uint32_t)((noff + brow) * ROWB + kb + bkh * 16);
                LDSM4(bh, st + OFF_BH + rb);
                LDSM4(bl, st + OFF_BL + rb);
            }
#pragma unroll
            for (int mi = 0; mi < 2; mi++)
#pragma unroll
                for (int nj = 0; nj < 2; nj++) {
                    const int p = nj * 2;
                    MMA(d[mi][nj], ah[mi], bh[p], bh[p + 1]);
                    MMA(d[mi][nj], ah[mi], bl[p], bl[p + 1]);
                }
        }
        if (s + 3 < NC) issue(s + 3);
        cpcommit();
    }

    // stage D (batch-major) into smem
    __syncthreads();
    float* cs = (float*)smem;                   // [64 batch][68] rows = gate*16+jin
    const int rr = lane >> 2, cc = (lane & 3) * 2;
#pragma unroll
    for (int mi = 0; mi < 2; mi++)
#pragma unroll
        for (int nj = 0; nj < 2; nj++) {
            int m = moff + mi * 16 + rr;
            int n = noff + nj * 8 + cc;
            cs[n * 68 + m]           = d[mi][nj][0];
            cs[(n + 1) * 68 + m]     = d[mi][nj][1];
            cs[n * 68 + m + 8]       = d[mi][nj][2];
            cs[(n + 1) * 68 + m + 8] = d[mi][nj][3];
        }
    __syncthreads();

    // pointwise: thread -> batch b, 4 hidden units
    const int b = t >> 2, j4 = (t & 3) * 4;
    const int jg0 = blockIdx.x * 16;
    float4 cold = *(const float4*)(c + (size_t)b * 2048 + jg0 + j4);
    float cn[4]; hf hi4[4], lo4[4];
#pragma unroll
    for (int q = 0; q < 4; q++) {
        const int j = j4 + q, jg = jg0 + j;
        float iv = cs[b * 68 + j];
        float fv = cs[b * 68 + 16 + j];
        float gv = cs[b * 68 + 32 + j];
        float ov = cs[b * 68 + 48 + j];
        if (pre) {
            iv += pre[(size_t)(jg) * 64 + b];
            fv += pre[(size_t)(2048 + jg) * 64 + b];
            gv += pre[(size_t)(4096 + jg) * 64 + b];
            ov += pre[(size_t)(6144 + jg) * 64 + b];
        }
        iv += bias[jg]; fv += bias[2048 + jg];
        gv += bias[4096 + jg]; ov += bias[6144 + jg];
        float si = 1.f / (1.f + __expf(-iv));
        float sf = 1.f / (1.f + __expf(-fv));
        float so = 1.f / (1.f + __expf(-ov));
        float c2 = sf * (&cold.x)[q] + si * tanhf(gv);
        float h2 = so * tanhf(c2);
        cn[q] = c2;
        hi4[q] = __float2half_rn(h2);
        lo4[q] = __float2half_rn(h2 - __half2float(hi4[q]));
    }
    *(float4*)(c + (size_t)b * 2048 + jg0 + j4) = *(float4*)cn;
    *(uint2*)(hh + (size_t)b * 2048 + jg0 + j4) = *(uint2*)hi4;
    *(uint2*)(hl + (size_t)b * 2048 + jg0 + j4) = *(uint2*)lo4;
}

extern "C" void kernel_launch(void* const* d_in, const int* in_sizes, int n_in,
                              void* d_out, int out_size)
{
    const float* x        = (const float*)d_in[0];
    const float* fc_en1_w = (const float*)d_in[1];
    const float* fc_en1_b = (const float*)d_in[2];
    const float* fc_en2_w = (const float*)d_in[3];
    const float* fc_en2_b = (const float*)d_in[4];
    const float* en_wih   = (const float*)d_in[5];
    const float* en_whh   = (const float*)d_in[6];
    const float* en_b     = (const float*)d_in[7];
    const float* de_wih   = (const float*)d_in[8];
    const float* de_whh   = (const float*)d_in[9];
    const float* de_b     = (const float*)d_in[10];
    const float* fc_de1_w = (const float*)d_in[11];
    const float* fc_de1_b = (const float*)d_in[12];
    const float* fc_de2_w = (const float*)d_in[13];
    const float* fc_de2_b = (const float*)d_in[14];
    float* out = (float*)d_out;

    hf *wcat, *ewhh0, *ewih0, *fc1w, *fc2w, *fd1w, *fd2w;
    hf *xh, *xl, *f1ah, *f1al, *f2ah, *f2al, *d1ah, *d1al, *hH, *hL;
    float *pre, *c;
    cudaGetSymbolAddress((void**)&wcat, g_wcat);
    cudaGetSymbolAddress((void**)&ewhh0, g_ewhh0);
    cudaGetSymbolAddress((void**)&ewih0, g_ewih0);
    cudaGetSymbolAddress((void**)&fc1w, g_fc1w);   cudaGetSymbolAddress((void**)&fc2w, g_fc2w);
    cudaGetSymbolAddress((void**)&fd1w, g_fd1w);   cudaGetSymbolAddress((void**)&fd2w, g_fd2w);
    cudaGetSymbolAddress((void**)&xh, g_xh);       cudaGetSymbolAddress((void**)&xl, g_xl);
    cudaGetSymbolAddress((void**)&f1ah, g_f1a_h);  cudaGetSymbolAddress((void**)&f1al, g_f1a_l);
    cudaGetSymbolAddress((void**)&f2ah, g_f2a_h);  cudaGetSymbolAddress((void**)&f2al, g_f2a_l);
    cudaGetSymbolAddress((void**)&d1ah, g_d1a_h);  cudaGetSymbolAddress((void**)&d1al, g_d1a_l);
    cudaGetSymbolAddress((void**)&hH, g_hH);       cudaGetSymbolAddress((void**)&hL, g_hL);
    cudaGetSymbolAddress((void**)&pre, g_pre);     cudaGetSymbolAddress((void**)&c, g_c);

    cudaFuncSetAttribute(gemm_ms,    cudaFuncAttributeMaxDynamicSharedMemorySize, SMEM_SZ);
    cudaFuncSetAttribute(lstm_fused, cudaFuncAttributeMaxDynamicSharedMemorySize, SMEM_SZ);

    const int HB = 131072;   // one [64,2048] slab (elems)
    // h buffer accessor: layer l, parity p
    auto HHp = [&](int l, int p) { return hH + (size_t)(l * 2 + p) * HB; };
    auto HLp = [&](int l, int p) { return hL + (size_t)(l * 2 + p) * HB; };

    // ---- prepass ----
    {
        SplitArgs a;
        const float* srcs[9] = {en_wih, fc_en1_w, fc_en2_w, fc_de1_w, fc_de2_w,
                                x, x, x, x};
        hf* hs[9] = {ewih0, fc1w, fc2w, fd1w, fd2w, xh, xh, xh, xh};
        hf* ls[9] = {nullptr, nullptr, nullptr, nullptr, nullptr,
                     xl, nullptr, nullptr, nullptr};
        long ns[9] = {LWF, 4194304, 2097152, 2097152, 4194304, 4194304, 0, 0, 0};
        long acc = 0;
        for (int i = 0; i < 9; i++) {
            a.s[i] = srcs[i]; a.h[i] = hs[i]; a.l[i] = ls[i];
            a.off4[i] = acc; acc += ns[i] / 4;
        }
        a.off4[9] = acc;
        split_all<<<1024, 256>>>(a);
    }
    // packed cat matrices: 0=enc l1, 1=enc l2, 2=dec l0, 3=dec l1, 4=dec l2
    lstm_pack<<<2048, 256>>>(en_wih + (size_t)1 * LWF, en_whh + (size_t)1 * LWF,
                             wcat + (size_t)0 * WCATN, 1);
    lstm_pack<<<2048, 256>>>(en_wih + (size_t)2 * LWF, en_whh + (size_t)2 * LWF,
                             wcat + (size_t)1 * WCATN, 1);
    lstm_pack<<<2048, 256>>>(de_wih,                   de_whh,
                             wcat + (size_t)2 * WCATN, 1);
    lstm_pack<<<2048, 256>>>(de_wih + (size_t)1 * LWF, de_whh + (size_t)1 * LWF,
                             wcat + (size_t)3 * WCATN, 1);
    lstm_pack<<<2048, 256>>>(de_wih + (size_t)2 * LWF, de_whh + (size_t)2 * LWF,
                             wcat + (size_t)4 * WCATN, 1);
    lstm_pack<<<1024, 256>>>(nullptr, en_whh, ewhh0, 0);

    cudaMemsetAsync(hH, 0, 6 * HB * sizeof(hf));
    cudaMemsetAsync(hL, 0, 6 * HB * sizeof(hf));
    cudaMemsetAsync(c,  0, 3 * HB * sizeof(float));

    // ---- encoder FCs + l0 pre-gates (batched over 16 steps) ----
    gemm_ms<<<dim3(16, 16), 256, SMEM_SZ>>>(fc1w, xh, xl, fc_en1_b,
        nullptr, f1ah, f1al, 4096, 1024, 1, 0);
    gemm_ms<<<dim3(32, 16), 256, SMEM_SZ>>>(fc2w, f1ah, f1al, fc_en2_b,
        nullptr, f2ah, f2al, 1024, 2048, 1, 0);
    gemm_ms<<<dim3(128, 16), 256, SMEM_SZ>>>(ewih0, f2ah, f2al, nullptr,
        pre, nullptr, nullptr, 2048, 0, 0, 2);

    // ---- encoder ----
    for (int t = 0; t < 16; t++) {
        const int rp = t & 1, wp = 1 - rp;
        lstm_fused<<<128, 256, SMEM_SZ>>>(ewhh0,
            nullptr, nullptr, HHp(0, rp), HLp(0, rp),
            pre + (size_t)t * 524288, en_b, c,
            HHp(0, wp), HLp(0, wp), 0);
        lstm_fused<<<128, 256, SMEM_SZ>>>(wcat + (size_t)0 * WCATN,
            HHp(0, wp), HLp(0, wp), HHp(1, rp), HLp(1, rp),
            nullptr, en_b + 8192, c + HB,
            HHp(1, wp), HLp(1, wp), 2048);
        lstm_fused<<<128, 256, SMEM_SZ>>>(wcat + (size_t)1 * WCATN,
            HHp(1, wp), HLp(1, wp), HHp(2, rp), HLp(2, rp),
            nullptr, en_b + 16384, c + 2 * HB,
            HHp(2, wp), HLp(2, wp), 2048);
    }

    // ---- decoder init ----
    // enc t=15 wrote parity 0. dec h0(p0) := enc h2(p0); h1,h2 (p0) zero; c zero.
    cudaMemcpyAsync(HHp(0, 0), HHp(2, 0), HB * sizeof(hf), cudaMemcpyDeviceToDevice);
    cudaMemcpyAsync(HLp(0, 0), HLp(2, 0), HB * sizeof(hf), cudaMemcpyDeviceToDevice);
    cudaMemsetAsync(HHp(1, 0), 0, HB * sizeof(hf));
    cudaMemsetAsync(HLp(1, 0), 0, HB * sizeof(hf));
    cudaMemsetAsync(HHp(2, 0), 0, HB * sizeof(hf));
    cudaMemsetAsync(HLp(2, 0), 0, HB * sizeof(hf));
    cudaMemsetAsync(c, 0, 3 * HB * sizeof(float));

    // ---- decoder ----
    for (int t = 0; t < 16; t++) {
        const int rp = t & 1, wp = 1 - rp;
        // l0: x = h2(t-1) [zero buffer at t=0], recurrent = h0(t-1)
        lstm_fused<<<128, 256, SMEM_SZ>>>(wcat + (size_t)2 * WCATN,
            HHp(2, rp), HLp(2, rp), HHp(0, rp), HLp(0, rp),
            nullptr, de_b, c,
            HHp(0, wp), HLp(0, wp), 2048);
        lstm_fused<<<128, 256, SMEM_SZ>>>(wcat + (size_t)3 * WCATN,
            HHp(0, wp), HLp(0, wp), HHp(1, rp), HLp(1, rp),
            nullptr, de_b + 8192, c + HB,
            HHp(1, wp), HLp(1, wp), 2048);
        lstm_fused<<<128, 256, SMEM_SZ>>>(wcat + (size_t)4 * WCATN,
            HHp(1, wp), HLp(1, wp), HHp(2, rp), HLp(2, rp),
            nullptr, de_b + 16384, c + 2 * HB,
            HHp(2, wp), HLp(2, wp), 2048);
        gemm_ms<<<dim3(16, 1), 256, SMEM_SZ>>>(fd1w, HHp(2, wp), HLp(2, wp),
            fc_de1_b, nullptr, d1ah, d1al, 2048, 1024, 1, 0);
        gemm_ms<<<dim3(64, 1), 256, SMEM_SZ>>>(fd2w, d1ah, d1al,
            fc_de2_b, out + (size_t)t * 262144, nullptr, nullptr, 1024, 4096, 2, 0);
    }
}

// round 9
// speedup vs baseline: 4.6586x; 1.0262x over previous
#include <cuda_runtime.h>
#include <cuda_fp16.h>
#include <cstdint>
#include <cstddef>

typedef __half hf;

// ---------------- tile constants ----------------
#define TM    64
#define ROWB  144
#define OFF_A  0
#define OFF_BH 9216
#define OFF_BL 18432
#define STAGE  27648
#define SMEM_SZ (4 * STAGE)       // 110592 B
#define NCTA  128
#define HB    131072              // 64*2048 elems

// ---------------- asm helpers ----------------
__device__ __forceinline__ void cpa(uint32_t d, const void* s) {
    asm volatile("cp.async.cg.shared.global [%0], [%1], 16;" :: "r"(d), "l"(s));
}
__device__ __forceinline__ void cpcommit() {
    asm volatile("cp.async.commit_group;" ::: "memory");
}
template <int N> __device__ __forceinline__ void cpwait() {
    asm volatile("cp.async.wait_group %0;" :: "n"(N) : "memory");
}
#define LDSM4(R, addr) \
    asm volatile("ldmatrix.sync.aligned.m8n8.x4.shared.b16 {%0,%1,%2,%3}, [%4];" \
        : "=r"((R)[0]), "=r"((R)[1]), "=r"((R)[2]), "=r"((R)[3]) : "r"(addr))
#define MMA(D, A, b0, b1) \
    asm volatile("mma.sync.aligned.m16n8k16.row.col.f32.f16.f16.f32 " \
        "{%0,%1,%2,%3}, {%4,%5,%6,%7}, {%8,%9}, {%0,%1,%2,%3};" \
        : "+f"((D)[0]), "+f"((D)[1]), "+f"((D)[2]), "+f"((D)[3]) \
        : "r"((A)[0]), "r"((A)[1]), "r"((A)[2]), "r"((A)[3]), "r"(b0), "r"(b1))

// ---------------- scratch ----------------
#define LWF 16777216               // 8192*2048 (one fp32 LSTM matrix, elems)
#define WCATN 33554432             // 8192*4096 per cat matrix
__device__ hf g_wcat[5 * WCATN];                     // enc l1,l2; dec l0,l1,l2
__device__ hf g_ewhh0[LWF];                          // enc l0 Whh, interleaved
__device__ hf g_ewih0[LWF];                          // enc l0 Wih, flat
__device__ hf g_fc1w[4194304], g_fc2w[2097152];
__device__ hf g_fd1w[2097152], g_fd2w[4194304];
__device__ hf g_xh[4194304],   g_xl[4194304];
__device__ hf g_f1a_h[1048576], g_f1a_l[1048576];
__device__ hf g_f2a_h[2097152], g_f2a_l[2097152];
__device__ hf g_d1a_h[65536],  g_d1a_l[65536];
__device__ hf g_hH[6 * HB], g_hL[6 * HB];            // [layer][parity]
__device__ float g_pre[16 * 524288];
__device__ float g_c[3 * HB];
__device__ unsigned g_bar[2];                        // cnt, gen

// ===========================================================================
// prepass kernels
// ===========================================================================
struct SplitArgs {
    const float* s[6];
    hf* h[6];
    hf* l[6];
    long off4[7];
};

__global__ void __launch_bounds__(256) split_all(SplitArgs a)
{
    const long total = a.off4[6];
    for (long v = (long)blockIdx.x * 256 + threadIdx.x; v < total;
         v += (long)gridDim.x * 256) {
        int seg = 0;
#pragma unroll
        for (int i = 0; i < 5; i++) seg += (v >= a.off4[i + 1]) ? 1 : 0;
        long e = (v - a.off4[seg]) * 4;
        float4 x = *(const float4*)(a.s[seg] + e);
        hf h0 = __float2half_rn(x.x), h1 = __float2half_rn(x.y);
        hf h2 = __float2half_rn(x.z), h3 = __float2half_rn(x.w);
        uint2 ph;
        ph.x = (uint32_t)*(uint16_t*)&h0 | ((uint32_t)*(uint16_t*)&h1 << 16);
        ph.y = (uint32_t)*(uint16_t*)&h2 | ((uint32_t)*(uint16_t*)&h3 << 16);
        *(uint2*)(a.h[seg] + e) = ph;
        if (a.l[seg]) {
            hf l0 = __float2half_rn(x.x - __half2float(h0));
            hf l1 = __float2half_rn(x.y - __half2float(h1));
            hf l2 = __float2half_rn(x.z - __half2float(h2));
            hf l3 = __float2half_rn(x.w - __half2float(h3));
            uint2 pl;
            pl.x = (uint32_t)*(uint16_t*)&l0 | ((uint32_t)*(uint16_t*)&l1 << 16);
            pl.y = (uint32_t)*(uint16_t*)&l2 | ((uint32_t)*(uint16_t*)&l3 << 16);
            *(uint2*)(a.l[seg] + e) = pl;
        }
    }
}

__global__ void __launch_bounds__(256) lstm_pack(
    const float* __restrict__ wih, const float* __restrict__ whh,
    hf* __restrict__ dst, int hasx)
{
    const int K = hasx ? 4096 : 2048;
    const long total = (long)8192 * K / 4;
    for (long v = (long)blockIdx.x * 256 + threadIdx.x; v < total;
         v += (long)gridDim.x * 256) {
        int r = (int)(v / (K >> 2));
        int c = (int)(v % (K >> 2)) * 4;
        int gate = (r >> 4) & 3, jblk = r >> 6, jin = r & 15;
        int orig = gate * 2048 + jblk * 16 + jin;
        const float* src = (c < 2048 || !hasx)
            ? (hasx ? wih : whh) + (size_t)orig * 2048 + (c & 2047)
            : whh + (size_t)orig * 2048 + (c - 2048);
        float4 x = *(const float4*)src;
        hf h0 = __float2half_rn(x.x), h1 = __float2half_rn(x.y);
        hf h2 = __float2half_rn(x.z), h3 = __float2half_rn(x.w);
        uint2 ph;
        ph.x = (uint32_t)*(uint16_t*)&h0 | ((uint32_t)*(uint16_t*)&h1 << 16);
        ph.y = (uint32_t)*(uint16_t*)&h2 | ((uint32_t)*(uint16_t*)&h3 << 16);
        *(uint2*)(dst + (size_t)r * K + c) = ph;
    }
}

// ===========================================================================
// shared GEMM mainloop (device)
// ===========================================================================
__device__ __forceinline__ void run_gemm(
    const hf* __restrict__ W, int K,
    const hf* __restrict__ BxH, const hf* __restrict__ BxL, int Kx, int ldbx,
    const hf* __restrict__ BhH, const hf* __restrict__ BhL, int ldbh,
    uint32_t sb, float acc[2][2][4])
{
    const int t = threadIdx.x;
    const int NC = K >> 6;
    const int r0 = t >> 3, seg = t & 7;
    __syncthreads();     // previous phase's smem use complete
    auto issue = [&](int chunk) {
        if (chunk < NC) {
            const uint32_t st = sb + (chunk & 3) * STAGE;
            const int kg = chunk << 6;
            const hf *bh, *bl; int ks, ldb;
            if (kg < Kx) { bh = BxH; bl = BxL; ks = kg; ldb = ldbx; }
            else         { bh = BhH; bl = BhL; ks = kg - Kx; ldb = ldbh; }
#pragma unroll
            for (int i = 0; i < 2; i++) {
                int row = r0 + i * 32;
                uint32_t dd = st + row * ROWB + seg * 16;
                cpa(dd + OFF_A,  W  + (size_t)row * K   + kg + seg * 8);
                cpa(dd + OFF_BH, bh + (size_t)row * ldb + ks + seg * 8);
                cpa(dd + OFF_BL, bl + (size_t)row * ldb + ks + seg * 8);
            }
        }
        cpcommit();
    };
    issue(0); issue(1); issue(2);

    const int w = t >> 5, lane = t & 31;
    const int moff = (w & 1) * 32, noff = (w >> 1) * 16;
    const int arow = lane & 15, ahalf = lane >> 4;
    const int bj = lane >> 3;
    const int brow = ((bj >> 1) * 8) + (lane & 7), bkh = bj & 1;

#pragma unroll
    for (int mi = 0; mi < 2; mi++)
#pragma unroll
        for (int nj = 0; nj < 2; nj++)
#pragma unroll
            for (int q = 0; q < 4; q++) acc[mi][nj][q] = 0.f;

    for (int s = 0; s < NC; s++) {
        cpwait<2>();
        __syncthreads();
        const uint32_t st = sb + (s & 3) * STAGE;
#pragma unroll
        for (int k16 = 0; k16 < 4; k16++) {
            const int kb = k16 * 32;
            uint32_t ah[2][4], bh[4], bl[4];
#pragma unroll
            for (int mi = 0; mi < 2; mi++) {
                uint32_t ra = (uint32_t)((moff + mi * 16 + arow) * ROWB + kb + ahalf * 16);
                LDSM4(ah[mi], st + OFF_A + ra);
            }
            uint32_t rb = (uint32_t)((noff + brow) * ROWB + kb + bkh * 16);
            LDSM4(bh, st + OFF_BH + rb);
            LDSM4(bl, st + OFF_BL + rb);
#pragma unroll
            for (int mi = 0; mi < 2; mi++)
#pragma unroll
                for (int nj = 0; nj < 2; nj++) {
                    const int p2 = nj * 2;
                    MMA(acc[mi][nj], ah[mi], bh[p2], bh[p2 + 1]);
                    MMA(acc[mi][nj], ah[mi], bl[p2], bl[p2 + 1]);
                }
        }
        issue(s + 3);
    }
}

// batch-major staging of acc into cs[64][68]
__device__ __forceinline__ void stage_cs(float acc[2][2][4], float* cs)
{
    const int t = threadIdx.x;
    const int w = t >> 5, lane = t & 31;
    const int moff = (w & 1) * 32, noff = (w >> 1) * 16;
    const int rr = lane >> 2, cc = (lane & 3) * 2;
    __syncthreads();
#pragma unroll
    for (int mi = 0; mi < 2; mi++)
#pragma unroll
        for (int nj = 0; nj < 2; nj++) {
            int m = moff + mi * 16 + rr;
            int n = noff + nj * 8 + cc;
            cs[n * 68 + m]           = acc[mi][nj][0];
            cs[(n + 1) * 68 + m]     = acc[mi][nj][1];
            cs[n * 68 + m + 8]       = acc[mi][nj][2];
            cs[(n + 1) * 68 + m + 8] = acc[mi][nj][3];
        }
    __syncthreads();
}

// grid barrier (all NCTA CTAs resident)
__device__ __forceinline__ void gbar(unsigned* cnt, unsigned* gen, unsigned& mygen)
{
    __threadfence();
    __syncthreads();
    if (threadIdx.x == 0) {
        mygen += 1;
        unsigned prev = atomicAdd(cnt, 1u);
        if (prev == NCTA - 1) {
            atomicExch(cnt, 0u);
            __threadfence();
            atomicExch(gen, mygen);
        } else {
            while (atomicAdd(gen, 0u) < mygen) __nanosleep(64);
        }
    }
    __syncthreads();
}

// ===========================================================================
// batched FC GEMM (prepass-stage, large grids)
// dual=2: f-major store to outf + y*524288 ; mode1: relu + hi/lo split
// ===========================================================================
__global__ void __launch_bounds__(256, 2)
gemm_ms(const hf* __restrict__ A0, const hf* __restrict__ Bh0, const hf* __restrict__ Bl0,
        const float* __restrict__ bias,
        float* __restrict__ outf, hf* __restrict__ outh, hf* __restrict__ outl,
        int K, int ldc, int dual)
{
    extern __shared__ char smem[];
    const uint32_t sb = (uint32_t)__cvta_generic_to_shared(smem);
    const int t = threadIdx.x;
    const int fbase = blockIdx.x * TM;
    const int nbase = blockIdx.y * 64;

    float acc[2][2][4];
    run_gemm(A0 + (size_t)fbase * K, K,
             Bh0 + (size_t)nbase * K, Bl0 + (size_t)nbase * K, K, K,
             nullptr, nullptr, 0, sb, acc);

    const int w = t >> 5, lane = t & 31;
    const int moff = (w & 1) * 32, noff = (w >> 1) * 16;
    const int rr = lane >> 2, cc = (lane & 3) * 2;

    if (dual == 2) {
        float* po = outf + (size_t)blockIdx.y * 524288;
#pragma unroll
        for (int mi = 0; mi < 2; mi++)
#pragma unroll
            for (int nj = 0; nj < 2; nj++) {
                int m = moff + mi * 16 + rr;
                int n = noff + nj * 8 + cc;
                *(float2*)(po + (size_t)(fbase + m) * 64 + n) =
                    make_float2(acc[mi][nj][0], acc[mi][nj][1]);
                *(float2*)(po + (size_t)(fbase + m + 8) * 64 + n) =
                    make_float2(acc[mi][nj][2], acc[mi][nj][3]);
            }
        return;
    }

    float* cs = (float*)smem;
    stage_cs(acc, cs);
    const int b = t >> 2, j0 = (t & 3) * 16;
    const float* bp = bias + fbase + j0;
    hf* dh = outh + (size_t)(nbase + b) * ldc + fbase + j0;
    hf* dl = outl + (size_t)(nbase + b) * ldc + fbase + j0;
#pragma unroll
    for (int j = 0; j < 16; j++) {
        float v = fmaxf(cs[b * 68 + j0 + j] + bp[j], 0.f);
        hf hi = __float2half_rn(v);
        dh[j] = hi;
        dl[j] = __float2half_rn(v - __half2float(hi));
    }
}

// ===========================================================================
// persistent LSTM kernels
// ===========================================================================
struct PP {
    const hf *wcat, *ewhh0;
    const float *pre, *en_b, *de_b;
    hf *hH, *hL;
    float *c;
    const hf *fd1w, *fd2w;
    const float *fd1b, *fd2b;
    hf *d1ah, *d1al;
    float *out;
    unsigned *bar;
};

__device__ __forceinline__ void lstm_cell_epi(
    float acc[2][2][4], float* cs, const float* pre, const float* bias,
    float* c, hf* hh, hf* hl, int jg0)
{
    stage_cs(acc, cs);
    const int t = threadIdx.x;
    const int b = t >> 2, j4 = (t & 3) * 4;
    float4 cold = *(const float4*)(c + (size_t)b * 2048 + jg0 + j4);
    float cn[4]; hf hi4[4], lo4[4];
#pragma unroll
    for (int q = 0; q < 4; q++) {
        const int j = j4 + q, jg = jg0 + j;
        float iv = cs[b * 68 + j];
        float fv = cs[b * 68 + 16 + j];
        float gv = cs[b * 68 + 32 + j];
        float ov = cs[b * 68 + 48 + j];
        if (pre) {
            iv += pre[(size_t)(jg) * 64 + b];
            fv += pre[(size_t)(2048 + jg) * 64 + b];
            gv += pre[(size_t)(4096 + jg) * 64 + b];
            ov += pre[(size_t)(6144 + jg) * 64 + b];
        }
        iv += bias[jg]; fv += bias[2048 + jg];
        gv += bias[4096 + jg]; ov += bias[6144 + jg];
        float si = 1.f / (1.f + __expf(-iv));
        float sf = 1.f / (1.f + __expf(-fv));
        float so = 1.f / (1.f + __expf(-ov));
        float c2 = sf * (&cold.x)[q] + si * tanhf(gv);
        float h2 = so * tanhf(c2);
        cn[q] = c2;
        hi4[q] = __float2half_rn(h2);
        lo4[q] = __float2half_rn(h2 - __half2float(hi4[q]));
    }
    *(float4*)(c + (size_t)b * 2048 + jg0 + j4) = *(float4*)cn;
    *(uint2*)(hh + (size_t)b * 2048 + jg0 + j4) = *(uint2*)hi4;
    *(uint2*)(hl + (size_t)b * 2048 + jg0 + j4) = *(uint2*)lo4;
}

__global__ void __launch_bounds__(256)
enc_persist(PP p)
{
    extern __shared__ char smem[];
    const uint32_t sb = (uint32_t)__cvta_generic_to_shared(smem);
    float* cs = (float*)smem;
    const int bid = blockIdx.x;
    const int fbase = bid * TM, jg0 = bid * 16;
    unsigned mygen = 0;
    float acc[2][2][4];
    auto HHp = [&](int l, int pr) { return p.hH + (size_t)(l * 2 + pr) * HB; };
    auto HLp = [&](int l, int pr) { return p.hL + (size_t)(l * 2 + pr) * HB; };

    for (int t16 = 0; t16 < 16; t16++) {
        const int rp = t16 & 1, wp = 1 - rp;
        // l0: Whh only + pre-gates
        run_gemm(p.ewhh0 + (size_t)fbase * 2048, 2048,
                 nullptr, nullptr, 0, 0,
                 HHp(0, rp), HLp(0, rp), 2048, sb, acc);
        lstm_cell_epi(acc, cs, p.pre + (size_t)t16 * 524288, p.en_b,
                      p.c, HHp(0, wp), HLp(0, wp), jg0);
        gbar(p.bar, p.bar + 1, mygen);
        // l1
        run_gemm(p.wcat + (size_t)0 * WCATN + (size_t)fbase * 4096, 4096,
                 HHp(0, wp), HLp(0, wp), 2048, 2048,
                 HHp(1, rp), HLp(1, rp), 2048, sb, acc);
        lstm_cell_epi(acc, cs, nullptr, p.en_b + 8192,
                      p.c + HB, HHp(1, wp), HLp(1, wp), jg0);
        gbar(p.bar, p.bar + 1, mygen);
        // l2
        run_gemm(p.wcat + (size_t)1 * WCATN + (size_t)fbase * 4096, 4096,
                 HHp(1, wp), HLp(1, wp), 2048, 2048,
                 HHp(2, rp), HLp(2, rp), 2048, sb, acc);
        lstm_cell_epi(acc, cs, nullptr, p.en_b + 16384,
                      p.c + 2 * HB, HHp(2, wp), HLp(2, wp), jg0);
        gbar(p.bar, p.bar + 1, mygen);
    }
}

__global__ void __launch_bounds__(256)
dec_persist(PP p)
{
    extern __shared__ char smem[];
    const uint32_t sb = (uint32_t)__cvta_generic_to_shared(smem);
    float* cs = (float*)smem;
    const int bid = blockIdx.x;
    const int fbase = bid * TM, jg0 = bid * 16;
    unsigned mygen = 0;
    float acc[2][2][4];
    auto HHp = [&](int l, int pr) { return p.hH + (size_t)(l * 2 + pr) * HB; };
    auto HLp = [&](int l, int pr) { return p.hL + (size_t)(l * 2 + pr) * HB; };

    for (int t16 = 0; t16 < 16; t16++) {
        const int rp = t16 & 1, wp = 1 - rp;
        // l0: x = h2(rp) (zero at t=0), rec = h0(rp)
        run_gemm(p.wcat + (size_t)2 * WCATN + (size_t)fbase * 4096, 4096,
                 HHp(2, rp), HLp(2, rp), 2048, 2048,
                 HHp(0, rp), HLp(0, rp), 2048, sb, acc);
        lstm_cell_epi(acc, cs, nullptr, p.de_b,
                      p.c, HHp(0, wp), HLp(0, wp), jg0);
        gbar(p.bar, p.bar + 1, mygen);
        // l1
        run_gemm(p.wcat + (size_t)3 * WCATN + (size_t)fbase * 4096, 4096,
                 HHp(0, wp), HLp(0, wp), 2048, 2048,
                 HHp(1, rp), HLp(1, rp), 2048, sb, acc);
        lstm_cell_epi(acc, cs, nullptr, p.de_b + 8192,
                      p.c + HB, HHp(1, wp), HLp(1, wp), jg0);
        gbar(p.bar, p.bar + 1, mygen);
        // l2
        run_gemm(p.wcat + (size_t)4 * WCATN + (size_t)fbase * 4096, 4096,
                 HHp(1, wp), HLp(1, wp), 2048, 2048,
                 HHp(2, rp), HLp(2, rp), 2048, sb, acc);
        lstm_cell_epi(acc, cs, nullptr, p.de_b + 16384,
                      p.c + 2 * HB, HHp(2, wp), HLp(2, wp), jg0);
        gbar(p.bar, p.bar + 1, mygen);
        // head: fd1 (relu + split) on CTAs 0..15
        if (bid < 16) {
            run_gemm(p.fd1w + (size_t)fbase * 2048, 2048,
                     HHp(2, wp), HLp(2, wp), 2048, 2048,
                     nullptr, nullptr, 0, sb, acc);
            stage_cs(acc, cs);
            const int t = threadIdx.x;
            const int b = t >> 2, j0 = (t & 3) * 16;
            const float* bp = p.fd1b + fbase + j0;
            hf* dh = p.d1ah + (size_t)b * 1024 + fbase + j0;
            hf* dl = p.d1al + (size_t)b * 1024 + fbase + j0;
#pragma unroll
            for (int j = 0; j < 16; j++) {
                float v = fmaxf(cs[b * 68 + j0 + j] + bp[j], 0.f);
                hf hi = __float2half_rn(v);
                dh[j] = hi;
                dl[j] = __float2half_rn(v - __half2float(hi));
            }
        }
        gbar(p.bar, p.bar + 1, mygen);
        // head: fd2 (sigmoid) on CTAs 0..63
        if (bid < 64) {
            run_gemm(p.fd2w + (size_t)fbase * 1024, 1024,
                     p.d1ah, p.d1al, 1024, 1024,
                     nullptr, nullptr, 0, sb, acc);
            stage_cs(acc, cs);
            const int t = threadIdx.x;
            const int b = t >> 2, j0 = (t & 3) * 16;
            const float* bp = p.fd2b + fbase + j0;
            float* dst = p.out + (size_t)t16 * 262144 + (size_t)b * 4096 + fbase + j0;
#pragma unroll
            for (int j = 0; j < 16; j++) {
                float v = cs[b * 68 + j0 + j] + bp[j];
                dst[j] = 1.f / (1.f + __expf(-v));
            }
        }
        gbar(p.bar, p.bar + 1, mygen);
    }
}

extern "C" void kernel_launch(void* const* d_in, const int* in_sizes, int n_in,
                              void* d_out, int out_size)
{
    const float* x        = (const float*)d_in[0];
    const float* fc_en1_w = (const float*)d_in[1];
    const float* fc_en1_b = (const float*)d_in[2];
    const float* fc_en2_w = (const float*)d_in[3];
    const float* fc_en2_b = (const float*)d_in[4];
    const float* en_wih   = (const float*)d_in[5];
    const float* en_whh   = (const float*)d_in[6];
    const float* en_b     = (const float*)d_in[7];
    const float* de_wih   = (const float*)d_in[8];
    const float* de_whh   = (const float*)d_in[9];
    const float* de_b     = (const float*)d_in[10];
    const float* fc_de1_w = (const float*)d_in[11];
    const float* fc_de1_b = (const float*)d_in[12];
    const float* fc_de2_w = (const float*)d_in[13];
    const float* fc_de2_b = (const float*)d_in[14];
    float* out = (float*)d_out;

    hf *wcat, *ewhh0, *ewih0, *fc1w, *fc2w, *fd1w, *fd2w;
    hf *xh, *xl, *f1ah, *f1al, *f2ah, *f2al, *d1ah, *d1al, *hH, *hL;
    float *pre, *c;
    unsigned* bar;
    cudaGetSymbolAddress((void**)&wcat, g_wcat);
    cudaGetSymbolAddress((void**)&ewhh0, g_ewhh0);
    cudaGetSymbolAddress((void**)&ewih0, g_ewih0);
    cudaGetSymbolAddress((void**)&fc1w, g_fc1w);   cudaGetSymbolAddress((void**)&fc2w, g_fc2w);
    cudaGetSymbolAddress((void**)&fd1w, g_fd1w);   cudaGetSymbolAddress((void**)&fd2w, g_fd2w);
    cudaGetSymbolAddress((void**)&xh, g_xh);       cudaGetSymbolAddress((void**)&xl, g_xl);
    cudaGetSymbolAddress((void**)&f1ah, g_f1a_h);  cudaGetSymbolAddress((void**)&f1al, g_f1a_l);
    cudaGetSymbolAddress((void**)&f2ah, g_f2a_h);  cudaGetSymbolAddress((void**)&f2al, g_f2a_l);
    cudaGetSymbolAddress((void**)&d1ah, g_d1a_h);  cudaGetSymbolAddress((void**)&d1al, g_d1a_l);
    cudaGetSymbolAddress((void**)&hH, g_hH);       cudaGetSymbolAddress((void**)&hL, g_hL);
    cudaGetSymbolAddress((void**)&pre, g_pre);     cudaGetSymbolAddress((void**)&c, g_c);
    cudaGetSymbolAddress((void**)&bar, g_bar);

    cudaFuncSetAttribute(gemm_ms,     cudaFuncAttributeMaxDynamicSharedMemorySize, SMEM_SZ);
    cudaFuncSetAttribute(enc_persist, cudaFuncAttributeMaxDynamicSharedMemorySize, SMEM_SZ);
    cudaFuncSetAttribute(dec_persist, cudaFuncAttributeMaxDynamicSharedMemorySize, SMEM_SZ);

    auto HHp = [&](int l, int pr) { return hH + (size_t)(l * 2 + pr) * HB; };
    auto HLp = [&](int l, int pr) { return hL + (size_t)(l * 2 + pr) * HB; };

    // ---- prepass ----
    {
        SplitArgs a;
        const float* srcs[6] = {en_wih, fc_en1_w, fc_en2_w, fc_de1_w, fc_de2_w, x};
        hf* hs[6] = {ewih0, fc1w, fc2w, fd1w, fd2w, xh};
        hf* ls[6] = {nullptr, nullptr, nullptr, nullptr, nullptr, xl};
        long ns[6] = {LWF, 4194304, 2097152, 2097152, 4194304, 4194304};
        long acc = 0;
        for (int i = 0; i < 6; i++) {
            a.s[i] = srcs[i]; a.h[i] = hs[i]; a.l[i] = ls[i];
            a.off4[i] = acc; acc += ns[i] / 4;
        }
        a.off4[6] = acc;
        split_all<<<1024, 256>>>(a);
    }
    lstm_pack<<<2048, 256>>>(en_wih + (size_t)1 * LWF, en_whh + (size_t)1 * LWF,
                             wcat + (size_t)0 * WCATN, 1);
    lstm_pack<<<2048, 256>>>(en_wih + (size_t)2 * LWF, en_whh + (size_t)2 * LWF,
                             wcat + (size_t)1 * WCATN, 1);
    lstm_pack<<<2048, 256>>>(de_wih,                   de_whh,
                             wcat + (size_t)2 * WCATN, 1);
    lstm_pack<<<2048, 256>>>(de_wih + (size_t)1 * LWF, de_whh + (size_t)1 * LWF,
                             wcat + (size_t)3 * WCATN, 1);
    lstm_pack<<<2048, 256>>>(de_wih + (size_t)2 * LWF, de_whh + (size_t)2 * LWF,
                             wcat + (size_t)4 * WCATN, 1);
    lstm_pack<<<1024, 256>>>(nullptr, en_whh, ewhh0, 0);

    cudaMemsetAsync(hH, 0, 6 * HB * sizeof(hf));
    cudaMemsetAsync(hL, 0, 6 * HB * sizeof(hf));
    cudaMemsetAsync(c,  0, 3 * HB * sizeof(float));

    // ---- batched encoder FCs + l0 pre-gates ----
    gemm_ms<<<dim3(16, 16), 256, SMEM_SZ>>>(fc1w, xh, xl, fc_en1_b,
        nullptr, f1ah, f1al, 4096, 1024, 0);
    gemm_ms<<<dim3(32, 16), 256, SMEM_SZ>>>(fc2w, f1ah, f1al, fc_en2_b,
        nullptr, f2ah, f2al, 1024, 2048, 0);
    gemm_ms<<<dim3(128, 16), 256, SMEM_SZ>>>(ewih0, f2ah, f2al, nullptr,
        pre, nullptr, nullptr, 2048, 0, 2);

    PP p;
    p.wcat = wcat; p.ewhh0 = ewhh0; p.pre = pre;
    p.en_b = en_b; p.de_b = de_b;
    p.hH = hH; p.hL = hL; p.c = c;
    p.fd1w = fd1w; p.fd2w = fd2w; p.fd1b = fc_de1_b; p.fd2b = fc_de2_b;
    p.d1ah = d1ah; p.d1al = d1al; p.out = out; p.bar = bar;

    // ---- encoder (one persistent launch) ----
    cudaMemsetAsync(bar, 0, 2 * sizeof(unsigned));
    enc_persist<<<NCTA, 256, SMEM_SZ>>>(p);

    // ---- decoder init: h0(p0) = enc h2(p0); h1,h2(p0) zero; c zero ----
    cudaMemcpyAsync(HHp(0, 0), HHp(2, 0), HB * sizeof(hf), cudaMemcpyDeviceToDevice);
    cudaMemcpyAsync(HLp(0, 0), HLp(2, 0), HB * sizeof(hf), cudaMemcpyDeviceToDevice);
    cudaMemsetAsync(HHp(1, 0), 0, HB * sizeof(hf));
    cudaMemsetAsync(HLp(1, 0), 0, HB * sizeof(hf));
    cudaMemsetAsync(HHp(2, 0), 0, HB * sizeof(hf));
    cudaMemsetAsync(HLp(2, 0), 0, HB * sizeof(hf));
    cudaMemsetAsync(c, 0, 3 * HB * sizeof(float));

    // ---- decoder (one persistent launch, head fused) ----
    cudaMemsetAsync(bar, 0, 2 * sizeof(unsigned));
    dec_persist<<<NCTA, 256, SMEM_SZ>>>(p);
}